// round 12
// baseline (speedup 1.0000x reference)
#include <cuda_runtime.h>
#include <cuda_bf16.h>
#include <math.h>
#include <stdint.h>

#define N_NODES 50000
#define N_EDGES 600000
#define C 128
#define EC 16
#define BN_EPS 1e-5f
#define ALPHA 0.5f

typedef __nv_bfloat16 bf16;
typedef __nv_bfloat162 bf162;

// ---------------- device scratch (no allocations allowed) ----------------
__device__ float g_xh[N_NODES * C];          // BN output (x0) fp32
__device__ bf16  g_xhh[N_NODES * C];         // BN output bf16 (GEMM A)
__device__ float g_h[N_NODES * C];           // h after layer 0 (fp32)
__device__ bf16  g_hh[N_NODES * C];          // h bf16 (GEMM A, layer 1)
__device__ bf16  g_ghh[N_NODES * 384];       // gh bf16 (fp32-accumulated, demoted)
__device__ bf16  g_gih[N_NODES * 384];       // gi bf16 (fp32-accumulated, demoted)
__device__ bf16  g_mh[N_NODES * C];          // bf16 copy of m (gather source)
__device__ bf16  g_aggh[N_NODES * C];        // (agg/deg) bf16 (GEMM2 A)
__device__ bf16  g_eah[N_EDGES * C];         // ea per EDGE (edge order), bf16
__device__ int   g_src[N_EDGES];
__device__ int   g_dst[N_EDGES];
__device__ int2  g_csr[N_EDGES];             // {src, eid} per CSR position
__device__ int   g_degi[N_NODES];
__device__ int   g_ptr[N_NODES + 1];
__device__ int   g_cur[N_NODES];
__device__ int   g_bsum[256];
__device__ int   g_boff[256];
__device__ float g_invdeg[N_NODES];
__device__ float g_sum[C];
__device__ float g_sq[C];
__device__ bf16  g_B0h[512 * 128];           // [convW0^T | w_hh] rows n, k contig
__device__ bf16  g_B1h[512 * 128];           // [convW1^T | w_hh]
__device__ bf16  g_B2h[384 * 128];           // w_ih (already [384][128] k-contig)
__device__ bf16  g_eWh[128 * 16];            // edge_W^T: [n][k] bf16
__device__ float g_bias512[512];             // [0...0 | b_hh]
__device__ int   g_is64;

// ---------------- small PTX helpers ----------------
__device__ __forceinline__ uint32_t smem_u32(const void* p) {
    uint32_t a;
    asm("{ .reg .u64 t; cvta.to.shared.u64 t, %1; cvt.u32.u64 %0, t; }"
        : "=r"(a) : "l"(p));
    return a;
}
__device__ __forceinline__ void ldmx4(uint32_t* r, uint32_t addr) {
    asm volatile("ldmatrix.sync.aligned.m8n8.x4.shared.b16 {%0,%1,%2,%3}, [%4];"
        : "=r"(r[0]), "=r"(r[1]), "=r"(r[2]), "=r"(r[3]) : "r"(addr));
}
__device__ __forceinline__ void mma_bf16(float* d, const uint32_t* a,
                                         const uint32_t* b) {
    asm volatile(
        "mma.sync.aligned.m16n8k16.row.col.f32.bf16.bf16.f32 "
        "{%0,%1,%2,%3}, {%4,%5,%6,%7}, {%8,%9}, {%0,%1,%2,%3};"
        : "+f"(d[0]), "+f"(d[1]), "+f"(d[2]), "+f"(d[3])
        : "r"(a[0]), "r"(a[1]), "r"(a[2]), "r"(a[3]), "r"(b[0]), "r"(b[1]));
}
__device__ __forceinline__ float sigm(float x) { return 1.f / (1.f + expf(-x)); }

// ---------------- edge_index dtype detection ----------------
__global__ void detect_kernel(const long long* __restrict__ raw) {
    __shared__ int bad;
    if (threadIdx.x == 0) bad = 0;
    __syncthreads();
    long long v = raw[threadIdx.x];   // 64 threads
    if (v < 0 || v >= (1LL << 31)) atomicExch(&bad, 1);
    __syncthreads();
    if (threadIdx.x == 0) g_is64 = bad ? 0 : 1;
}

// normalize + degree count fused
__global__ void normalize_edges(const void* __restrict__ raw) {
    int e = blockIdx.x * blockDim.x + threadIdx.x;
    if (e >= N_EDGES) return;
    int s, d;
    if (g_is64) {
        const long long* p = (const long long*)raw;
        s = (int)p[e];
        d = (int)p[N_EDGES + e];
    } else {
        const int* p = (const int*)raw;
        s = p[e];
        d = p[N_EDGES + e];
    }
    g_src[e] = s;
    g_dst[e] = d;
    atomicAdd(&g_degi[d], 1);
}

__global__ void zero_deg() {
    int i = blockIdx.x * blockDim.x + threadIdx.x;
    if (i < N_NODES) g_degi[i] = 0;
}

__global__ void zero_bn() {
    int i = threadIdx.x;
    if (i < C) { g_sum[i] = 0.f; g_sq[i] = 0.f; }
}

#define SCAN_BLOCKS 196
__global__ void scan_part() {           // 196 x 256
    __shared__ int sh[256];
    int i = blockIdx.x * 256 + threadIdx.x;
    sh[threadIdx.x] = (i < N_NODES) ? g_degi[i] : 0;
    __syncthreads();
    for (int s = 128; s > 0; s >>= 1) {
        if (threadIdx.x < s) sh[threadIdx.x] += sh[threadIdx.x + s];
        __syncthreads();
    }
    if (threadIdx.x == 0) g_bsum[blockIdx.x] = sh[0];
}

__global__ void scan_top() {            // 1 x 256
    __shared__ int sh[256];
    int t = threadIdx.x;
    int own = (t < SCAN_BLOCKS) ? g_bsum[t] : 0;
    sh[t] = own;
    __syncthreads();
    for (int s = 1; s < 256; s <<= 1) {
        int v = (t >= s) ? sh[t - s] : 0;
        __syncthreads();
        sh[t] += v;
        __syncthreads();
    }
    if (t < SCAN_BLOCKS) g_boff[t] = sh[t] - own;   // exclusive
}

__global__ void scan_block() {          // 196 x 256, + invdeg fused
    __shared__ int sh[256];
    int t = threadIdx.x;
    int i = blockIdx.x * 256 + t;
    int v = (i < N_NODES) ? g_degi[i] : 0;
    sh[t] = v;
    __syncthreads();
    for (int s = 1; s < 256; s <<= 1) {
        int u = (t >= s) ? sh[t - s] : 0;
        __syncthreads();
        sh[t] += u;
        __syncthreads();
    }
    int excl = sh[t] - v + g_boff[blockIdx.x];
    if (i < N_NODES) {
        g_ptr[i] = excl;
        g_cur[i] = excl;
        g_invdeg[i] = 1.0f / fmaxf((float)v, 1.0f);
    }
    if (i == N_NODES - 1) g_ptr[N_NODES] = excl + v;
}

__global__ void scatter_k() {
    int e = blockIdx.x * blockDim.x + threadIdx.x;
    if (e >= N_EDGES) return;
    int s = g_src[e];
    int pos = atomicAdd(&g_cur[g_dst[e]], 1);
    g_csr[pos] = make_int2(s, e);
}

// ---------------- batchnorm ----------------
// 512 x 256; thread = (4-channel group, 4-row slice); 4 independent LDG.128.
__global__ void bn_stats(const float* __restrict__ x) {
    int c4 = (threadIdx.x & 31) * 4;
    int rl = threadIdx.x >> 5;           // 0..7
    float4 s = make_float4(0.f, 0.f, 0.f, 0.f);
    float4 q = make_float4(0.f, 0.f, 0.f, 0.f);
    int stride = gridDim.x * 32;
    for (int r = blockIdx.x * 32 + rl * 4; r < N_NODES; r += stride) {
        float4 v0 = make_float4(0.f, 0.f, 0.f, 0.f), v1 = v0, v2 = v0, v3 = v0;
        if (r + 0 < N_NODES) v0 = *(const float4*)(x + (size_t)(r + 0) * C + c4);
        if (r + 1 < N_NODES) v1 = *(const float4*)(x + (size_t)(r + 1) * C + c4);
        if (r + 2 < N_NODES) v2 = *(const float4*)(x + (size_t)(r + 2) * C + c4);
        if (r + 3 < N_NODES) v3 = *(const float4*)(x + (size_t)(r + 3) * C + c4);
        s.x += (v0.x + v1.x) + (v2.x + v3.x);
        s.y += (v0.y + v1.y) + (v2.y + v3.y);
        s.z += (v0.z + v1.z) + (v2.z + v3.z);
        s.w += (v0.w + v1.w) + (v2.w + v3.w);
        q.x += (v0.x * v0.x + v1.x * v1.x) + (v2.x * v2.x + v3.x * v3.x);
        q.y += (v0.y * v0.y + v1.y * v1.y) + (v2.y * v2.y + v3.y * v3.y);
        q.z += (v0.z * v0.z + v1.z * v1.z) + (v2.z * v2.z + v3.z * v3.z);
        q.w += (v0.w * v0.w + v1.w * v1.w) + (v2.w * v2.w + v3.w * v3.w);
    }
    atomicAdd(&g_sum[c4 + 0], s.x);
    atomicAdd(&g_sum[c4 + 1], s.y);
    atomicAdd(&g_sum[c4 + 2], s.z);
    atomicAdd(&g_sum[c4 + 3], s.w);
    atomicAdd(&g_sq[c4 + 0], q.x);
    atomicAdd(&g_sq[c4 + 1], q.y);
    atomicAdd(&g_sq[c4 + 2], q.z);
    atomicAdd(&g_sq[c4 + 3], q.w);
}

// bn_apply with bn_coef fused: each thread derives its 4 channel coefs
__global__ void bn_apply(const float* __restrict__ x,
                         const float* __restrict__ gamma,
                         const float* __restrict__ beta) {
    int idx = blockIdx.x * blockDim.x + threadIdx.x;   // float4 index
    if (idx >= N_NODES * C / 4) return;
    int c4 = (idx & 31) * 4;
    float4 su = *(const float4*)&g_sum[c4];
    float4 sq = *(const float4*)&g_sq[c4];
    float4 gm = *(const float4*)(gamma + c4);
    float4 bt = *(const float4*)(beta + c4);
    float4 sc, sh;
#pragma unroll
    for (int j = 0; j < 4; j++) {
        float mean = (&su.x)[j] / (float)N_NODES;
        float var = (&sq.x)[j] / (float)N_NODES - mean * mean;
        float s = (&gm.x)[j] * rsqrtf(var + BN_EPS);
        (&sc.x)[j] = s;
        (&sh.x)[j] = (&bt.x)[j] - mean * s;
    }
    float4 v = *(const float4*)(x + (size_t)idx * 4);
    v.x = v.x * sc.x + sh.x;
    v.y = v.y * sc.y + sh.y;
    v.z = v.z * sc.z + sh.z;
    v.w = v.w * sc.w + sh.w;
    *(float4*)&g_xh[(size_t)idx * 4] = v;
    bf162 p0 = __float22bfloat162_rn(make_float2(v.x, v.y));
    bf162 p1 = __float22bfloat162_rn(make_float2(v.z, v.w));
    uint2 st;
    st.x = *(uint32_t*)&p0;
    st.y = *(uint32_t*)&p1;
    *(uint2*)&g_xhh[(size_t)idx * 4] = st;
}

// ---------------- weight prep (bf16) ----------------
__global__ void prep_eW(const float* __restrict__ eW) {
    int t = threadIdx.x + blockIdx.x * blockDim.x;
    if (t < 128 * 16) {
        int nn = t >> 4, kk = t & 15;
        g_eWh[t] = __float2bfloat16(eW[kk * 128 + nn]);
    }
}

__global__ void prep_weights(const float* __restrict__ convW,
                             const float* __restrict__ w_ih,
                             const float* __restrict__ w_hh,
                             const float* __restrict__ b_hh) {
    int idx = blockIdx.x * blockDim.x + threadIdx.x;
    int total = 512 * 128;
    for (int t = idx; t < total; t += gridDim.x * blockDim.x) {
        int n = t >> 7;
        int k = t & 127;
        float v0, v1;
        if (n < 128) {
            v0 = convW[k * 128 + n];
            v1 = convW[128 * 128 + k * 128 + n];
        } else {
            float w = w_hh[(n - 128) * 128 + k];
            v0 = w; v1 = w;
        }
        g_B0h[t] = __float2bfloat16(v0);
        g_B1h[t] = __float2bfloat16(v1);
        if (t < 384 * 128) g_B2h[t] = __float2bfloat16(w_ih[t]);
        if (t < 512) g_bias512[t] = (t < 128) ? 0.f : b_hh[t - 128];
    }
}

// ---------------- bf16 tensor-core GEMM ----------------
// C = A[M x 128] @ Bt^T + bias, accumulated fp32, stored bf16.
// gh_mode=1: cols<128 -> bf16 mcopy (m); cols>=128 -> bf16 Cmat stride 384 (gh).
// gh_mode=0: bf16 Cmat stride nb (gi).
#define SPADH 136
#define ASH_BYTES (128 * SPADH * 2)
#define TILE_SMEM (2 * ASH_BYTES)

__global__ __launch_bounds__(256, 2)
void gemm_bf16(const bf16* __restrict__ A, const bf16* __restrict__ Bt, int nb,
               const float* __restrict__ bias, bf16* __restrict__ Cmat,
               bf16* __restrict__ mcopy, int gh_mode, int M) {
    extern __shared__ bf16 smh[];
    bf16* As = smh;                     // [128][SPADH]
    bf16* Bs = smh + 128 * SPADH;

    int tid = threadIdx.x, wid = tid >> 5, lane = tid & 31;
    int rowBase = blockIdx.y * 128, colBase = blockIdx.x * 128;
    uint32_t As_u = smem_u32(As), Bs_u = smem_u32(Bs);

#pragma unroll
    for (int i = 0; i < 8; i++) {
        int c = tid + i * 256;
        int r = c >> 4, o = c & 15;
        int grow = rowBase + r;
        uint32_t sa = As_u + r * (SPADH * 2) + o * 16;
        int gr = (grow < M) ? grow : (M - 1);
        const void* ga = A + (size_t)gr * 128 + o * 8;
        uint32_t sz = (grow < M) ? 16u : 0u;
        asm volatile("cp.async.cg.shared.global [%0], [%1], 16, %2;"
                     :: "r"(sa), "l"(ga), "r"(sz));
    }
#pragma unroll
    for (int i = 0; i < 8; i++) {
        int c = tid + i * 256;
        int r = c >> 4, o = c & 15;
        uint32_t sa = Bs_u + r * (SPADH * 2) + o * 16;
        const void* ga = Bt + (size_t)(colBase + r) * 128 + o * 8;
        asm volatile("cp.async.cg.shared.global [%0], [%1], 16;"
                     :: "r"(sa), "l"(ga));
    }
    asm volatile("cp.async.commit_group;");
    asm volatile("cp.async.wait_group 0;" ::: "memory");
    __syncthreads();

    int mBase = (wid >> 2) * 64, nBase = (wid & 3) * 32;
    int mat = lane >> 3, rin = lane & 7;

    uint32_t aAddr[4];
#pragma unroll
    for (int mi = 0; mi < 4; mi++) {
        int row = mBase + mi * 16 + (mat & 1) * 8 + rin;
        int koff = (mat >> 1) * 8;
        aAddr[mi] = As_u + row * (SPADH * 2) + koff * 2;
    }
    uint32_t bAddr[2];
#pragma unroll
    for (int j = 0; j < 2; j++) {
        int row = nBase + j * 16 + (mat >> 1) * 8 + rin;
        int koff = (mat & 1) * 8;
        bAddr[j] = Bs_u + row * (SPADH * 2) + koff * 2;
    }

    float acc[4][4][4] = {};
#pragma unroll
    for (int ks = 0; ks < 8; ks++) {
        uint32_t afr[4][4], bfr[2][4];
#pragma unroll
        for (int mi = 0; mi < 4; mi++) ldmx4(afr[mi], aAddr[mi] + ks * 32);
#pragma unroll
        for (int j = 0; j < 2; j++) ldmx4(bfr[j], bAddr[j] + ks * 32);
#pragma unroll
        for (int mi = 0; mi < 4; mi++) {
            mma_bf16(acc[mi][0], afr[mi], &bfr[0][0]);
            mma_bf16(acc[mi][1], afr[mi], &bfr[0][2]);
            mma_bf16(acc[mi][2], afr[mi], &bfr[1][0]);
            mma_bf16(acc[mi][3], afr[mi], &bfr[1][2]);
        }
    }

    int qr = lane >> 2, qc = lane & 3;
#pragma unroll
    for (int mi = 0; mi < 4; mi++) {
        int r0 = rowBase + mBase + mi * 16 + qr;
#pragma unroll
        for (int ni = 0; ni < 4; ni++) {
            int cc = colBase + nBase + ni * 8 + qc * 2;
            float2 bv = *(const float2*)(bias + cc);
            bf162 h0 = __float22bfloat162_rn(
                make_float2(acc[mi][ni][0] + bv.x, acc[mi][ni][1] + bv.y));
            bf162 h1 = __float22bfloat162_rn(
                make_float2(acc[mi][ni][2] + bv.x, acc[mi][ni][3] + bv.y));
            if (gh_mode) {
                if (cc < 128) {
                    if (r0 < M)
                        *(bf162*)(mcopy + (size_t)r0 * 128 + cc) = h0;
                    if (r0 + 8 < M)
                        *(bf162*)(mcopy + (size_t)(r0 + 8) * 128 + cc) = h1;
                } else {
                    if (r0 < M)
                        *(bf162*)(Cmat + (size_t)r0 * 384 + (cc - 128)) = h0;
                    if (r0 + 8 < M)
                        *(bf162*)(Cmat + (size_t)(r0 + 8) * 384 + (cc - 128)) = h1;
                }
            } else {
                if (r0 < M) *(bf162*)(Cmat + (size_t)r0 * nb + cc) = h0;
                if (r0 + 8 < M) *(bf162*)(Cmat + (size_t)(r0 + 8) * nb + cc) = h1;
            }
        }
    }
}

// ---------------- ea GEMM: [600k x 16] @ [16 x 128] -> bf16, EDGE order --------
#define SPADE 24
__global__ __launch_bounds__(256, 4)
void ea_gemm(const float* __restrict__ eattr) {
    __shared__ bf16 As[128 * SPADE];
    __shared__ bf16 Bs[128 * SPADE];

    int tid = threadIdx.x, wid = tid >> 5, lane = tid & 31;
    int rowBase = blockIdx.x * 128;
    uint32_t As_u = smem_u32(As), Bs_u = smem_u32(Bs);

    {
        int r = tid >> 1, part = tid & 1;
        int p = rowBase + r;
        int row = (p < N_EDGES) ? p : (N_EDGES - 1);
        const float4* src = (const float4*)(eattr + (size_t)row * 16 + part * 8);
        float4 v0 = src[0], v1 = src[1];
        bf162 h0 = __float22bfloat162_rn(make_float2(v0.x, v0.y));
        bf162 h1 = __float22bfloat162_rn(make_float2(v0.z, v0.w));
        bf162 h2 = __float22bfloat162_rn(make_float2(v1.x, v1.y));
        bf162 h3 = __float22bfloat162_rn(make_float2(v1.z, v1.w));
        uint4 st;
        st.x = *(uint32_t*)&h0; st.y = *(uint32_t*)&h1;
        st.z = *(uint32_t*)&h2; st.w = *(uint32_t*)&h3;
        *(uint4*)&As[r * SPADE + part * 8] = st;
    }
    {
        int r = tid >> 1, part = tid & 1;
        uint4 v = *(const uint4*)&g_eWh[r * 16 + part * 8];
        *(uint4*)&Bs[r * SPADE + part * 8] = v;
    }
    __syncthreads();

    int mBase = (wid >> 2) * 64, nBase = (wid & 3) * 32;
    int mat = lane >> 3, rin = lane & 7;

    uint32_t afr[4][4], bfr[2][4];
#pragma unroll
    for (int mi = 0; mi < 4; mi++) {
        int row = mBase + mi * 16 + (mat & 1) * 8 + rin;
        int koff = (mat >> 1) * 8;
        ldmx4(afr[mi], As_u + row * (SPADE * 2) + koff * 2);
    }
#pragma unroll
    for (int j = 0; j < 2; j++) {
        int row = nBase + j * 16 + (mat >> 1) * 8 + rin;
        int koff = (mat & 1) * 8;
        ldmx4(bfr[j], Bs_u + row * (SPADE * 2) + koff * 2);
    }

    float acc[4][4][4] = {};
#pragma unroll
    for (int mi = 0; mi < 4; mi++) {
        mma_bf16(acc[mi][0], afr[mi], &bfr[0][0]);
        mma_bf16(acc[mi][1], afr[mi], &bfr[0][2]);
        mma_bf16(acc[mi][2], afr[mi], &bfr[1][0]);
        mma_bf16(acc[mi][3], afr[mi], &bfr[1][2]);
    }

    int qr = lane >> 2, qc = lane & 3;
#pragma unroll
    for (int mi = 0; mi < 4; mi++) {
        int r0 = rowBase + mBase + mi * 16 + qr;
#pragma unroll
        for (int ni = 0; ni < 4; ni++) {
            int cc = nBase + ni * 8 + qc * 2;
            if (r0 < N_EDGES)
                *(bf162*)(g_eah + (size_t)r0 * 128 + cc) =
                    __float22bfloat162_rn(make_float2(acc[mi][ni][0],
                                                      acc[mi][ni][1]));
            if (r0 + 8 < N_EDGES)
                *(bf162*)(g_eah + (size_t)(r0 + 8) * 128 + cc) =
                    __float22bfloat162_rn(make_float2(acc[mi][ni][2],
                                                      acc[mi][ni][3]));
        }
    }
}

// ---------------- CSR aggregation: one warp per node ----------------
__global__ void agg_csr() {
    int warp = (blockIdx.x * blockDim.x + threadIdx.x) >> 5;
    int lane = threadIdx.x & 31;
    if (warp >= N_NODES) return;

    int beg = g_ptr[warp], end = g_ptr[warp + 1];
    float4 acc = make_float4(0.f, 0.f, 0.f, 0.f);

    for (int e = beg; e < end; e++) {
        int2 se = g_csr[e];
        uint2 ev = *(const uint2*)&g_eah[(size_t)se.y * C + lane * 4];
        uint2 mv = *(const uint2*)&g_mh[(size_t)se.x * C + lane * 4];
        float2 e01 = __bfloat1622float2(*(bf162*)&ev.x);
        float2 e23 = __bfloat1622float2(*(bf162*)&ev.y);
        float2 m01 = __bfloat1622float2(*(bf162*)&mv.x);
        float2 m23 = __bfloat1622float2(*(bf162*)&mv.y);
        acc.x += fmaxf(m01.x + e01.x, 0.f);
        acc.y += fmaxf(m01.y + e01.y, 0.f);
        acc.z += fmaxf(m23.x + e23.x, 0.f);
        acc.w += fmaxf(m23.y + e23.y, 0.f);
    }
    float sc = g_invdeg[warp];
    bf162 p0 = __float22bfloat162_rn(make_float2(acc.x * sc, acc.y * sc));
    bf162 p1 = __float22bfloat162_rn(make_float2(acc.z * sc, acc.w * sc));
    uint2 st;
    st.x = *(uint32_t*)&p0;
    st.y = *(uint32_t*)&p1;
    *(uint2*)&g_aggh[(size_t)warp * C + lane * 4] = st;
}

// ---------------- GRU gates (bf16 gi/gh in, fp32 math) ----------------
__global__ void gru_gates(const float* __restrict__ hin,
                          float* __restrict__ hout, bf16* __restrict__ houth,
                          int last) {
    int idx = blockIdx.x * blockDim.x + threadIdx.x;   // 4-elem chunk index
    if (idx >= N_NODES * C / 4) return;
    int n = idx >> 5;
    int c4 = (idx & 31) * 4;
    const bf16* gib = g_gih + (size_t)n * 384;
    const bf16* ghb = g_ghh + (size_t)n * 384;

    uint2 u_ir = *(const uint2*)(gib + c4);
    uint2 u_iz = *(const uint2*)(gib + 128 + c4);
    uint2 u_in = *(const uint2*)(gib + 256 + c4);
    uint2 u_hr = *(const uint2*)(ghb + c4);
    uint2 u_hz = *(const uint2*)(ghb + 128 + c4);
    uint2 u_hn = *(const uint2*)(ghb + 256 + c4);
    float4 hv = *(const float4*)(hin + (size_t)idx * 4);

    float ir[4], iz[4], in_[4], hr[4], hz[4], hn[4];
    {
        float2 a, b;
        a = __bfloat1622float2(*(bf162*)&u_ir.x); b = __bfloat1622float2(*(bf162*)&u_ir.y);
        ir[0] = a.x; ir[1] = a.y; ir[2] = b.x; ir[3] = b.y;
        a = __bfloat1622float2(*(bf162*)&u_iz.x); b = __bfloat1622float2(*(bf162*)&u_iz.y);
        iz[0] = a.x; iz[1] = a.y; iz[2] = b.x; iz[3] = b.y;
        a = __bfloat1622float2(*(bf162*)&u_in.x); b = __bfloat1622float2(*(bf162*)&u_in.y);
        in_[0] = a.x; in_[1] = a.y; in_[2] = b.x; in_[3] = b.y;
        a = __bfloat1622float2(*(bf162*)&u_hr.x); b = __bfloat1622float2(*(bf162*)&u_hr.y);
        hr[0] = a.x; hr[1] = a.y; hr[2] = b.x; hr[3] = b.y;
        a = __bfloat1622float2(*(bf162*)&u_hz.x); b = __bfloat1622float2(*(bf162*)&u_hz.y);
        hz[0] = a.x; hz[1] = a.y; hz[2] = b.x; hz[3] = b.y;
        a = __bfloat1622float2(*(bf162*)&u_hn.x); b = __bfloat1622float2(*(bf162*)&u_hn.y);
        hn[0] = a.x; hn[1] = a.y; hn[2] = b.x; hn[3] = b.y;
    }

    float4 o;
#pragma unroll
    for (int j = 0; j < 4; j++) {
        float hj = (&hv.x)[j];
        float r = sigm(ir[j] + hr[j]);
        float z = sigm(iz[j] + hz[j]);
        float nn = tanhf(in_[j] + r * hn[j]);
        (&o.x)[j] = (1.f - z) * nn + z * hj;
    }

    if (last) {
        float4 xv = *(const float4*)(g_xh + (size_t)idx * 4);
        o.x = 0.5f * fmaxf(o.x, 0.f) + 0.5f * xv.x;
        o.y = 0.5f * fmaxf(o.y, 0.f) + 0.5f * xv.y;
        o.z = 0.5f * fmaxf(o.z, 0.f) + 0.5f * xv.z;
        o.w = 0.5f * fmaxf(o.w, 0.f) + 0.5f * xv.w;
        *(float4*)(hout + (size_t)idx * 4) = o;
    } else {
        *(float4*)(hout + (size_t)idx * 4) = o;
        bf162 p0 = __float22bfloat162_rn(make_float2(o.x, o.y));
        bf162 p1 = __float22bfloat162_rn(make_float2(o.z, o.w));
        uint2 st;
        st.x = *(uint32_t*)&p0;
        st.y = *(uint32_t*)&p1;
        *(uint2*)&houth[(size_t)idx * 4] = st;
    }
}

// ---------------- host ----------------
extern "C" void kernel_launch(void* const* d_in, const int* in_sizes, int n_in,
                              void* d_out, int out_size) {
    const float* x     = (const float*)d_in[0];
    const void*  eidx  = d_in[1];
    const float* eattr = (const float*)d_in[2];
    const float* gamma = (const float*)d_in[3];
    const float* beta  = (const float*)d_in[4];
    const float* edgeW = (const float*)d_in[5];
    const float* convW = (const float*)d_in[6];
    const float* w_ih  = (const float*)d_in[7];
    const float* w_hh  = (const float*)d_in[8];
    const float* b_ih  = (const float*)d_in[9];
    const float* b_hh  = (const float*)d_in[10];
    float* out = (float*)d_out;
    (void)in_sizes; (void)n_in; (void)out_size;

    float *xh, *h, *bias512;
    bf16 *xhh, *hh, *ghh, *gih, *mh, *aggh, *B0h, *B1h, *B2h;
    void* p;
    cudaGetSymbolAddress(&p, g_xh);      xh = (float*)p;
    cudaGetSymbolAddress(&p, g_xhh);     xhh = (bf16*)p;
    cudaGetSymbolAddress(&p, g_h);       h = (float*)p;
    cudaGetSymbolAddress(&p, g_hh);      hh = (bf16*)p;
    cudaGetSymbolAddress(&p, g_ghh);     ghh = (bf16*)p;
    cudaGetSymbolAddress(&p, g_gih);     gih = (bf16*)p;
    cudaGetSymbolAddress(&p, g_mh);      mh = (bf16*)p;
    cudaGetSymbolAddress(&p, g_aggh);    aggh = (bf16*)p;
    cudaGetSymbolAddress(&p, g_B0h);     B0h = (bf16*)p;
    cudaGetSymbolAddress(&p, g_B1h);     B1h = (bf16*)p;
    cudaGetSymbolAddress(&p, g_B2h);     B2h = (bf16*)p;
    cudaGetSymbolAddress(&p, g_bias512); bias512 = (float*)p;

    cudaFuncSetAttribute(gemm_bf16, cudaFuncAttributeMaxDynamicSharedMemorySize,
                         TILE_SMEM);

    // one-time stream/event setup (on the non-captured correctness call)
    static cudaStream_t s2 = nullptr, s3 = nullptr;
    static cudaEvent_t evF = nullptr, evJ = nullptr, evE = nullptr, evW = nullptr;
    if (s2 == nullptr) {
        cudaStreamCreateWithFlags(&s2, cudaStreamNonBlocking);
        cudaStreamCreateWithFlags(&s3, cudaStreamNonBlocking);
        cudaEventCreateWithFlags(&evF, cudaEventDisableTiming);
        cudaEventCreateWithFlags(&evJ, cudaEventDisableTiming);
        cudaEventCreateWithFlags(&evE, cudaEventDisableTiming);
        cudaEventCreateWithFlags(&evW, cudaEventDisableTiming);
    }

    const int NC = N_NODES * C;
    const int mtiles = (N_NODES + 127) / 128;      // 391
    const int etiles = (N_EDGES + 127) / 128;      // 4688

    // root
    detect_kernel<<<1, 64>>>((const long long*)eidx);
    cudaEventRecord(evF, 0);
    cudaStreamWaitEvent(s2, evF, 0);
    cudaStreamWaitEvent(s3, evF, 0);

    // ---- chain C (weights + ea, edge order) on s3 ----
    prep_weights<<<256, 256, 0, s3>>>(convW, w_ih, w_hh, b_hh);
    cudaEventRecord(evW, s3);
    prep_eW<<<8, 256, 0, s3>>>(edgeW);
    ea_gemm<<<etiles, 256, 0, s3>>>(eattr);
    cudaEventRecord(evE, s3);

    // ---- chain B (graph/CSR) on s2 ----
    zero_deg<<<(N_NODES + 255) / 256, 256, 0, s2>>>();
    normalize_edges<<<(N_EDGES + 255) / 256, 256, 0, s2>>>(eidx);
    scan_part<<<SCAN_BLOCKS, 256, 0, s2>>>();
    scan_top<<<1, 256, 0, s2>>>();
    scan_block<<<SCAN_BLOCKS, 256, 0, s2>>>();
    scatter_k<<<(N_EDGES + 255) / 256, 256, 0, s2>>>();
    cudaEventRecord(evJ, s2);

    // ---- chain A (BN + layer-0 GEMM1) on capture stream ----
    zero_bn<<<1, 128>>>();
    bn_stats<<<512, 256>>>(x);
    bn_apply<<<(NC / 4 + 255) / 256, 256>>>(x, gamma, beta);
    cudaStreamWaitEvent(0, evW, 0);     // gemm1 needs B0h/bias512
    gemm_bf16<<<dim3(4, mtiles), 256, TILE_SMEM>>>(xhh, B0h, 512, bias512,
                                                   ghh, mh, 1, N_NODES);

    // join: agg needs CSR (B) + eah (C)
    cudaStreamWaitEvent(0, evJ, 0);
    cudaStreamWaitEvent(0, evE, 0);

    // layer 0
    agg_csr<<<(N_NODES + 7) / 8, 256>>>();
    gemm_bf16<<<dim3(3, mtiles), 256, TILE_SMEM>>>(aggh, B2h, 384, b_ih,
                                                   gih, nullptr, 0, N_NODES);
    gru_gates<<<(NC / 4 + 255) / 256, 256>>>(xh, h, hh, 0);

    // layer 1
    gemm_bf16<<<dim3(4, mtiles), 256, TILE_SMEM>>>(hh, B1h, 512, bias512,
                                                   ghh, mh, 1, N_NODES);
    agg_csr<<<(N_NODES + 7) / 8, 256>>>();
    gemm_bf16<<<dim3(3, mtiles), 256, TILE_SMEM>>>(aggh, B2h, 384, b_ih,
                                                   gih, nullptr, 0, N_NODES);
    gru_gates<<<(NC / 4 + 255) / 256, 256>>>(h, out, nullptr, 1);
}

// round 13
// speedup vs baseline: 1.3735x; 1.3735x over previous
#include <cuda_runtime.h>
#include <cuda_bf16.h>
#include <math.h>
#include <stdint.h>

#define N_NODES 50000
#define N_EDGES 600000
#define C 128
#define EC 16
#define BN_EPS 1e-5f
#define ALPHA 0.5f

typedef __nv_bfloat16 bf16;
typedef __nv_bfloat162 bf162;

// ---------------- device scratch (no allocations allowed) ----------------
__device__ float g_xh[N_NODES * C];          // BN output (x0) fp32
__device__ bf16  g_xhh[N_NODES * C];         // BN output bf16 (GEMM A)
__device__ float g_h[N_NODES * C];           // h after layer 0 (fp32)
__device__ bf16  g_hh[N_NODES * C];          // h bf16 (GEMM A, layer 1)
__device__ bf16  g_ghh[N_NODES * 384];       // gh bf16 (fp32-accumulated, demoted)
__device__ bf16  g_gih[N_NODES * 384];       // gi bf16 (fp32-accumulated, demoted)
__device__ bf16  g_mh[N_NODES * C];          // bf16 copy of m (gather source)
__device__ bf16  g_aggh[N_NODES * C];        // (agg/deg) bf16 (GEMM2 A)
__device__ bf16  g_eah[N_EDGES * C];         // ea per EDGE (edge order), bf16
__device__ int   g_src[N_EDGES];
__device__ int   g_dst[N_EDGES];
__device__ int2  g_csr[N_EDGES];             // {src, eid} per CSR position
__device__ int   g_degi[N_NODES];
__device__ int   g_ptr[N_NODES + 1];
__device__ int   g_cur[N_NODES];
__device__ int   g_bsum[256];
__device__ int   g_boff[256];
__device__ float g_invdeg[N_NODES];
__device__ float g_sum[C];
__device__ float g_sq[C];
__device__ bf16  g_B0h[512 * 128];           // [convW0^T | w_hh] rows n, k contig
__device__ bf16  g_B1h[512 * 128];           // [convW1^T | w_hh]
__device__ bf16  g_B2h[384 * 128];           // w_ih (already [384][128] k-contig)
__device__ bf16  g_eWh[128 * 16];            // edge_W^T: [n][k] bf16
__device__ float g_bias512[512];             // [0...0 | b_hh]
__device__ int   g_is64;

// ---------------- small PTX helpers ----------------
__device__ __forceinline__ uint32_t smem_u32(const void* p) {
    uint32_t a;
    asm("{ .reg .u64 t; cvta.to.shared.u64 t, %1; cvt.u32.u64 %0, t; }"
        : "=r"(a) : "l"(p));
    return a;
}
__device__ __forceinline__ void ldmx4(uint32_t* r, uint32_t addr) {
    asm volatile("ldmatrix.sync.aligned.m8n8.x4.shared.b16 {%0,%1,%2,%3}, [%4];"
        : "=r"(r[0]), "=r"(r[1]), "=r"(r[2]), "=r"(r[3]) : "r"(addr));
}
__device__ __forceinline__ void mma_bf16(float* d, const uint32_t* a,
                                         const uint32_t* b) {
    asm volatile(
        "mma.sync.aligned.m16n8k16.row.col.f32.bf16.bf16.f32 "
        "{%0,%1,%2,%3}, {%4,%5,%6,%7}, {%8,%9}, {%0,%1,%2,%3};"
        : "+f"(d[0]), "+f"(d[1]), "+f"(d[2]), "+f"(d[3])
        : "r"(a[0]), "r"(a[1]), "r"(a[2]), "r"(a[3]), "r"(b[0]), "r"(b[1]));
}
__device__ __forceinline__ float sigm(float x) { return 1.f / (1.f + expf(-x)); }

// ---------------- edge_index dtype detection ----------------
__global__ void detect_kernel(const long long* __restrict__ raw) {
    __shared__ int bad;
    if (threadIdx.x == 0) bad = 0;
    __syncthreads();
    long long v = raw[threadIdx.x];   // 64 threads
    if (v < 0 || v >= (1LL << 31)) atomicExch(&bad, 1);
    __syncthreads();
    if (threadIdx.x == 0) g_is64 = bad ? 0 : 1;
}

// normalize + degree count fused
__global__ void normalize_edges(const void* __restrict__ raw) {
    int e = blockIdx.x * blockDim.x + threadIdx.x;
    if (e >= N_EDGES) return;
    int s, d;
    if (g_is64) {
        const long long* p = (const long long*)raw;
        s = (int)p[e];
        d = (int)p[N_EDGES + e];
    } else {
        const int* p = (const int*)raw;
        s = p[e];
        d = p[N_EDGES + e];
    }
    g_src[e] = s;
    g_dst[e] = d;
    atomicAdd(&g_degi[d], 1);
}

__global__ void zero_deg() {
    int i = blockIdx.x * blockDim.x + threadIdx.x;
    if (i < N_NODES) g_degi[i] = 0;
}

__global__ void zero_bn() {
    int i = threadIdx.x;
    if (i < C) { g_sum[i] = 0.f; g_sq[i] = 0.f; }
}

#define SCAN_BLOCKS 196
__global__ void scan_part() {           // 196 x 256
    __shared__ int sh[256];
    int i = blockIdx.x * 256 + threadIdx.x;
    sh[threadIdx.x] = (i < N_NODES) ? g_degi[i] : 0;
    __syncthreads();
    for (int s = 128; s > 0; s >>= 1) {
        if (threadIdx.x < s) sh[threadIdx.x] += sh[threadIdx.x + s];
        __syncthreads();
    }
    if (threadIdx.x == 0) g_bsum[blockIdx.x] = sh[0];
}

__global__ void scan_top() {            // 1 x 256
    __shared__ int sh[256];
    int t = threadIdx.x;
    int own = (t < SCAN_BLOCKS) ? g_bsum[t] : 0;
    sh[t] = own;
    __syncthreads();
    for (int s = 1; s < 256; s <<= 1) {
        int v = (t >= s) ? sh[t - s] : 0;
        __syncthreads();
        sh[t] += v;
        __syncthreads();
    }
    if (t < SCAN_BLOCKS) g_boff[t] = sh[t] - own;   // exclusive
}

__global__ void scan_block() {          // 196 x 256, + invdeg fused
    __shared__ int sh[256];
    int t = threadIdx.x;
    int i = blockIdx.x * 256 + t;
    int v = (i < N_NODES) ? g_degi[i] : 0;
    sh[t] = v;
    __syncthreads();
    for (int s = 1; s < 256; s <<= 1) {
        int u = (t >= s) ? sh[t - s] : 0;
        __syncthreads();
        sh[t] += u;
        __syncthreads();
    }
    int excl = sh[t] - v + g_boff[blockIdx.x];
    if (i < N_NODES) {
        g_ptr[i] = excl;
        g_cur[i] = excl;
        g_invdeg[i] = 1.0f / fmaxf((float)v, 1.0f);
    }
    if (i == N_NODES - 1) g_ptr[N_NODES] = excl + v;
}

__global__ void scatter_k() {
    int e = blockIdx.x * blockDim.x + threadIdx.x;
    if (e >= N_EDGES) return;
    int s = g_src[e];
    int pos = atomicAdd(&g_cur[g_dst[e]], 1);
    g_csr[pos] = make_int2(s, e);
}

// ---------------- batchnorm (R11-verified version) ----------------
__global__ void bn_stats(const float* __restrict__ x) {
    int c = threadIdx.x & 127;
    int half = threadIdx.x >> 7;
    float s = 0.f, q = 0.f;
    int stride = gridDim.x * 8;
    for (int base = blockIdx.x * 8 + half * 4; base < N_NODES; base += stride) {
        float v0 = 0.f, v1 = 0.f, v2 = 0.f, v3 = 0.f;
        if (base + 0 < N_NODES) v0 = x[(size_t)(base + 0) * C + c];
        if (base + 1 < N_NODES) v1 = x[(size_t)(base + 1) * C + c];
        if (base + 2 < N_NODES) v2 = x[(size_t)(base + 2) * C + c];
        if (base + 3 < N_NODES) v3 = x[(size_t)(base + 3) * C + c];
        s += (v0 + v1) + (v2 + v3);
        q += (v0 * v0 + v1 * v1) + (v2 * v2 + v3 * v3);
    }
    atomicAdd(&g_sum[c], s);
    atomicAdd(&g_sq[c], q);
}

// bn_apply with bn_coef fused: each thread derives its 4 channel coefs
__global__ void bn_apply(const float* __restrict__ x,
                         const float* __restrict__ gamma,
                         const float* __restrict__ beta) {
    int idx = blockIdx.x * blockDim.x + threadIdx.x;   // float4 index
    if (idx >= N_NODES * C / 4) return;
    int c4 = (idx & 31) * 4;
    float4 su = *(const float4*)&g_sum[c4];
    float4 sq = *(const float4*)&g_sq[c4];
    float4 gm = *(const float4*)(gamma + c4);
    float4 bt = *(const float4*)(beta + c4);
    float4 sc, sh;
#pragma unroll
    for (int j = 0; j < 4; j++) {
        float mean = (&su.x)[j] / (float)N_NODES;
        float var = (&sq.x)[j] / (float)N_NODES - mean * mean;
        float s = (&gm.x)[j] * rsqrtf(var + BN_EPS);
        (&sc.x)[j] = s;
        (&sh.x)[j] = (&bt.x)[j] - mean * s;
    }
    float4 v = *(const float4*)(x + (size_t)idx * 4);
    v.x = v.x * sc.x + sh.x;
    v.y = v.y * sc.y + sh.y;
    v.z = v.z * sc.z + sh.z;
    v.w = v.w * sc.w + sh.w;
    *(float4*)&g_xh[(size_t)idx * 4] = v;
    bf162 p0 = __float22bfloat162_rn(make_float2(v.x, v.y));
    bf162 p1 = __float22bfloat162_rn(make_float2(v.z, v.w));
    uint2 st;
    st.x = *(uint32_t*)&p0;
    st.y = *(uint32_t*)&p1;
    *(uint2*)&g_xhh[(size_t)idx * 4] = st;
}

// ---------------- weight prep (bf16) ----------------
__global__ void prep_eW(const float* __restrict__ eW) {
    int t = threadIdx.x + blockIdx.x * blockDim.x;
    if (t < 128 * 16) {
        int nn = t >> 4, kk = t & 15;
        g_eWh[t] = __float2bfloat16(eW[kk * 128 + nn]);
    }
}

__global__ void prep_weights(const float* __restrict__ convW,
                             const float* __restrict__ w_ih,
                             const float* __restrict__ w_hh,
                             const float* __restrict__ b_hh) {
    int idx = blockIdx.x * blockDim.x + threadIdx.x;
    int total = 512 * 128;
    for (int t = idx; t < total; t += gridDim.x * blockDim.x) {
        int n = t >> 7;
        int k = t & 127;
        float v0, v1;
        if (n < 128) {
            v0 = convW[k * 128 + n];
            v1 = convW[128 * 128 + k * 128 + n];
        } else {
            float w = w_hh[(n - 128) * 128 + k];
            v0 = w; v1 = w;
        }
        g_B0h[t] = __float2bfloat16(v0);
        g_B1h[t] = __float2bfloat16(v1);
        if (t < 384 * 128) g_B2h[t] = __float2bfloat16(w_ih[t]);
        if (t < 512) g_bias512[t] = (t < 128) ? 0.f : b_hh[t - 128];
    }
}

// ---------------- bf16 tensor-core GEMM ----------------
// C = A[M x 128] @ Bt^T + bias, accumulated fp32, stored bf16.
// gh_mode=1: cols<128 -> bf16 mcopy (m); cols>=128 -> bf16 Cmat stride 384 (gh).
// gh_mode=0: bf16 Cmat stride nb (gi).
#define SPADH 136
#define ASH_BYTES (128 * SPADH * 2)
#define TILE_SMEM (2 * ASH_BYTES)

__global__ __launch_bounds__(256, 2)
void gemm_bf16(const bf16* __restrict__ A, const bf16* __restrict__ Bt, int nb,
               const float* __restrict__ bias, bf16* __restrict__ Cmat,
               bf16* __restrict__ mcopy, int gh_mode, int M) {
    extern __shared__ bf16 smh[];
    bf16* As = smh;                     // [128][SPADH]
    bf16* Bs = smh + 128 * SPADH;

    int tid = threadIdx.x, wid = tid >> 5, lane = tid & 31;
    int rowBase = blockIdx.y * 128, colBase = blockIdx.x * 128;
    uint32_t As_u = smem_u32(As), Bs_u = smem_u32(Bs);

#pragma unroll
    for (int i = 0; i < 8; i++) {
        int c = tid + i * 256;
        int r = c >> 4, o = c & 15;
        int grow = rowBase + r;
        uint32_t sa = As_u + r * (SPADH * 2) + o * 16;
        int gr = (grow < M) ? grow : (M - 1);
        const void* ga = A + (size_t)gr * 128 + o * 8;
        uint32_t sz = (grow < M) ? 16u : 0u;
        asm volatile("cp.async.cg.shared.global [%0], [%1], 16, %2;"
                     :: "r"(sa), "l"(ga), "r"(sz));
    }
#pragma unroll
    for (int i = 0; i < 8; i++) {
        int c = tid + i * 256;
        int r = c >> 4, o = c & 15;
        uint32_t sa = Bs_u + r * (SPADH * 2) + o * 16;
        const void* ga = Bt + (size_t)(colBase + r) * 128 + o * 8;
        asm volatile("cp.async.cg.shared.global [%0], [%1], 16;"
                     :: "r"(sa), "l"(ga));
    }
    asm volatile("cp.async.commit_group;");
    asm volatile("cp.async.wait_group 0;" ::: "memory");
    __syncthreads();

    int mBase = (wid >> 2) * 64, nBase = (wid & 3) * 32;
    int mat = lane >> 3, rin = lane & 7;

    uint32_t aAddr[4];
#pragma unroll
    for (int mi = 0; mi < 4; mi++) {
        int row = mBase + mi * 16 + (mat & 1) * 8 + rin;
        int koff = (mat >> 1) * 8;
        aAddr[mi] = As_u + row * (SPADH * 2) + koff * 2;
    }
    uint32_t bAddr[2];
#pragma unroll
    for (int j = 0; j < 2; j++) {
        int row = nBase + j * 16 + (mat >> 1) * 8 + rin;
        int koff = (mat & 1) * 8;
        bAddr[j] = Bs_u + row * (SPADH * 2) + koff * 2;
    }

    float acc[4][4][4] = {};
#pragma unroll
    for (int ks = 0; ks < 8; ks++) {
        uint32_t afr[4][4], bfr[2][4];
#pragma unroll
        for (int mi = 0; mi < 4; mi++) ldmx4(afr[mi], aAddr[mi] + ks * 32);
#pragma unroll
        for (int j = 0; j < 2; j++) ldmx4(bfr[j], bAddr[j] + ks * 32);
#pragma unroll
        for (int mi = 0; mi < 4; mi++) {
            mma_bf16(acc[mi][0], afr[mi], &bfr[0][0]);
            mma_bf16(acc[mi][1], afr[mi], &bfr[0][2]);
            mma_bf16(acc[mi][2], afr[mi], &bfr[1][0]);
            mma_bf16(acc[mi][3], afr[mi], &bfr[1][2]);
        }
    }

    int qr = lane >> 2, qc = lane & 3;
#pragma unroll
    for (int mi = 0; mi < 4; mi++) {
        int r0 = rowBase + mBase + mi * 16 + qr;
#pragma unroll
        for (int ni = 0; ni < 4; ni++) {
            int cc = colBase + nBase + ni * 8 + qc * 2;
            float2 bv = *(const float2*)(bias + cc);
            bf162 h0 = __float22bfloat162_rn(
                make_float2(acc[mi][ni][0] + bv.x, acc[mi][ni][1] + bv.y));
            bf162 h1 = __float22bfloat162_rn(
                make_float2(acc[mi][ni][2] + bv.x, acc[mi][ni][3] + bv.y));
            if (gh_mode) {
                if (cc < 128) {
                    if (r0 < M)
                        *(bf162*)(mcopy + (size_t)r0 * 128 + cc) = h0;
                    if (r0 + 8 < M)
                        *(bf162*)(mcopy + (size_t)(r0 + 8) * 128 + cc) = h1;
                } else {
                    if (r0 < M)
                        *(bf162*)(Cmat + (size_t)r0 * 384 + (cc - 128)) = h0;
                    if (r0 + 8 < M)
                        *(bf162*)(Cmat + (size_t)(r0 + 8) * 384 + (cc - 128)) = h1;
                }
            } else {
                if (r0 < M) *(bf162*)(Cmat + (size_t)r0 * nb + cc) = h0;
                if (r0 + 8 < M) *(bf162*)(Cmat + (size_t)(r0 + 8) * nb + cc) = h1;
            }
        }
    }
}

// ---------------- ea GEMM: [600k x 16] @ [16 x 128] -> bf16, EDGE order --------
#define SPADE 24
__global__ __launch_bounds__(256, 4)
void ea_gemm(const float* __restrict__ eattr) {
    __shared__ bf16 As[128 * SPADE];
    __shared__ bf16 Bs[128 * SPADE];

    int tid = threadIdx.x, wid = tid >> 5, lane = tid & 31;
    int rowBase = blockIdx.x * 128;
    uint32_t As_u = smem_u32(As), Bs_u = smem_u32(Bs);

    {
        int r = tid >> 1, part = tid & 1;
        int p = rowBase + r;
        int row = (p < N_EDGES) ? p : (N_EDGES - 1);
        const float4* src = (const float4*)(eattr + (size_t)row * 16 + part * 8);
        float4 v0 = src[0], v1 = src[1];
        bf162 h0 = __float22bfloat162_rn(make_float2(v0.x, v0.y));
        bf162 h1 = __float22bfloat162_rn(make_float2(v0.z, v0.w));
        bf162 h2 = __float22bfloat162_rn(make_float2(v1.x, v1.y));
        bf162 h3 = __float22bfloat162_rn(make_float2(v1.z, v1.w));
        uint4 st;
        st.x = *(uint32_t*)&h0; st.y = *(uint32_t*)&h1;
        st.z = *(uint32_t*)&h2; st.w = *(uint32_t*)&h3;
        *(uint4*)&As[r * SPADE + part * 8] = st;
    }
    {
        int r = tid >> 1, part = tid & 1;
        uint4 v = *(const uint4*)&g_eWh[r * 16 + part * 8];
        *(uint4*)&Bs[r * SPADE + part * 8] = v;
    }
    __syncthreads();

    int mBase = (wid >> 2) * 64, nBase = (wid & 3) * 32;
    int mat = lane >> 3, rin = lane & 7;

    uint32_t afr[4][4], bfr[2][4];
#pragma unroll
    for (int mi = 0; mi < 4; mi++) {
        int row = mBase + mi * 16 + (mat & 1) * 8 + rin;
        int koff = (mat >> 1) * 8;
        ldmx4(afr[mi], As_u + row * (SPADE * 2) + koff * 2);
    }
#pragma unroll
    for (int j = 0; j < 2; j++) {
        int row = nBase + j * 16 + (mat >> 1) * 8 + rin;
        int koff = (mat & 1) * 8;
        ldmx4(bfr[j], Bs_u + row * (SPADE * 2) + koff * 2);
    }

    float acc[4][4][4] = {};
#pragma unroll
    for (int mi = 0; mi < 4; mi++) {
        mma_bf16(acc[mi][0], afr[mi], &bfr[0][0]);
        mma_bf16(acc[mi][1], afr[mi], &bfr[0][2]);
        mma_bf16(acc[mi][2], afr[mi], &bfr[1][0]);
        mma_bf16(acc[mi][3], afr[mi], &bfr[1][2]);
    }

    int qr = lane >> 2, qc = lane & 3;
#pragma unroll
    for (int mi = 0; mi < 4; mi++) {
        int r0 = rowBase + mBase + mi * 16 + qr;
#pragma unroll
        for (int ni = 0; ni < 4; ni++) {
            int cc = nBase + ni * 8 + qc * 2;
            if (r0 < N_EDGES)
                *(bf162*)(g_eah + (size_t)r0 * 128 + cc) =
                    __float22bfloat162_rn(make_float2(acc[mi][ni][0],
                                                      acc[mi][ni][1]));
            if (r0 + 8 < N_EDGES)
                *(bf162*)(g_eah + (size_t)(r0 + 8) * 128 + cc) =
                    __float22bfloat162_rn(make_float2(acc[mi][ni][2],
                                                      acc[mi][ni][3]));
        }
    }
}

// ---------------- CSR aggregation: one warp per node ----------------
__global__ void agg_csr() {
    int warp = (blockIdx.x * blockDim.x + threadIdx.x) >> 5;
    int lane = threadIdx.x & 31;
    if (warp >= N_NODES) return;

    int beg = g_ptr[warp], end = g_ptr[warp + 1];
    float4 acc = make_float4(0.f, 0.f, 0.f, 0.f);

    for (int e = beg; e < end; e++) {
        int2 se = g_csr[e];
        uint2 ev = *(const uint2*)&g_eah[(size_t)se.y * C + lane * 4];
        uint2 mv = *(const uint2*)&g_mh[(size_t)se.x * C + lane * 4];
        float2 e01 = __bfloat1622float2(*(bf162*)&ev.x);
        float2 e23 = __bfloat1622float2(*(bf162*)&ev.y);
        float2 m01 = __bfloat1622float2(*(bf162*)&mv.x);
        float2 m23 = __bfloat1622float2(*(bf162*)&mv.y);
        acc.x += fmaxf(m01.x + e01.x, 0.f);
        acc.y += fmaxf(m01.y + e01.y, 0.f);
        acc.z += fmaxf(m23.x + e23.x, 0.f);
        acc.w += fmaxf(m23.y + e23.y, 0.f);
    }
    float sc = g_invdeg[warp];
    bf162 p0 = __float22bfloat162_rn(make_float2(acc.x * sc, acc.y * sc));
    bf162 p1 = __float22bfloat162_rn(make_float2(acc.z * sc, acc.w * sc));
    uint2 st;
    st.x = *(uint32_t*)&p0;
    st.y = *(uint32_t*)&p1;
    *(uint2*)&g_aggh[(size_t)warp * C + lane * 4] = st;
}

// ---------------- GRU gates (bf16 gi/gh in, fp32 math) ----------------
__global__ void gru_gates(const float* __restrict__ hin,
                          float* __restrict__ hout, bf16* __restrict__ houth,
                          int last) {
    int idx = blockIdx.x * blockDim.x + threadIdx.x;   // 4-elem chunk index
    if (idx >= N_NODES * C / 4) return;
    int n = idx >> 5;
    int c4 = (idx & 31) * 4;
    const bf16* gib = g_gih + (size_t)n * 384;
    const bf16* ghb = g_ghh + (size_t)n * 384;

    uint2 u_ir = *(const uint2*)(gib + c4);
    uint2 u_iz = *(const uint2*)(gib + 128 + c4);
    uint2 u_in = *(const uint2*)(gib + 256 + c4);
    uint2 u_hr = *(const uint2*)(ghb + c4);
    uint2 u_hz = *(const uint2*)(ghb + 128 + c4);
    uint2 u_hn = *(const uint2*)(ghb + 256 + c4);
    float4 hv = *(const float4*)(hin + (size_t)idx * 4);

    float ir[4], iz[4], in_[4], hr[4], hz[4], hn[4];
    {
        float2 a, b;
        a = __bfloat1622float2(*(bf162*)&u_ir.x); b = __bfloat1622float2(*(bf162*)&u_ir.y);
        ir[0] = a.x; ir[1] = a.y; ir[2] = b.x; ir[3] = b.y;
        a = __bfloat1622float2(*(bf162*)&u_iz.x); b = __bfloat1622float2(*(bf162*)&u_iz.y);
        iz[0] = a.x; iz[1] = a.y; iz[2] = b.x; iz[3] = b.y;
        a = __bfloat1622float2(*(bf162*)&u_in.x); b = __bfloat1622float2(*(bf162*)&u_in.y);
        in_[0] = a.x; in_[1] = a.y; in_[2] = b.x; in_[3] = b.y;
        a = __bfloat1622float2(*(bf162*)&u_hr.x); b = __bfloat1622float2(*(bf162*)&u_hr.y);
        hr[0] = a.x; hr[1] = a.y; hr[2] = b.x; hr[3] = b.y;
        a = __bfloat1622float2(*(bf162*)&u_hz.x); b = __bfloat1622float2(*(bf162*)&u_hz.y);
        hz[0] = a.x; hz[1] = a.y; hz[2] = b.x; hz[3] = b.y;
        a = __bfloat1622float2(*(bf162*)&u_hn.x); b = __bfloat1622float2(*(bf162*)&u_hn.y);
        hn[0] = a.x; hn[1] = a.y; hn[2] = b.x; hn[3] = b.y;
    }

    float4 o;
#pragma unroll
    for (int j = 0; j < 4; j++) {
        float hj = (&hv.x)[j];
        float r = sigm(ir[j] + hr[j]);
        float z = sigm(iz[j] + hz[j]);
        float nn = tanhf(in_[j] + r * hn[j]);
        (&o.x)[j] = (1.f - z) * nn + z * hj;
    }

    if (last) {
        float4 xv = *(const float4*)(g_xh + (size_t)idx * 4);
        o.x = 0.5f * fmaxf(o.x, 0.f) + 0.5f * xv.x;
        o.y = 0.5f * fmaxf(o.y, 0.f) + 0.5f * xv.y;
        o.z = 0.5f * fmaxf(o.z, 0.f) + 0.5f * xv.z;
        o.w = 0.5f * fmaxf(o.w, 0.f) + 0.5f * xv.w;
        *(float4*)(hout + (size_t)idx * 4) = o;
    } else {
        *(float4*)(hout + (size_t)idx * 4) = o;
        bf162 p0 = __float22bfloat162_rn(make_float2(o.x, o.y));
        bf162 p1 = __float22bfloat162_rn(make_float2(o.z, o.w));
        uint2 st;
        st.x = *(uint32_t*)&p0;
        st.y = *(uint32_t*)&p1;
        *(uint2*)&houth[(size_t)idx * 4] = st;
    }
}

// ---------------- host ----------------
extern "C" void kernel_launch(void* const* d_in, const int* in_sizes, int n_in,
                              void* d_out, int out_size) {
    const float* x     = (const float*)d_in[0];
    const void*  eidx  = d_in[1];
    const float* eattr = (const float*)d_in[2];
    const float* gamma = (const float*)d_in[3];
    const float* beta  = (const float*)d_in[4];
    const float* edgeW = (const float*)d_in[5];
    const float* convW = (const float*)d_in[6];
    const float* w_ih  = (const float*)d_in[7];
    const float* w_hh  = (const float*)d_in[8];
    const float* b_ih  = (const float*)d_in[9];
    const float* b_hh  = (const float*)d_in[10];
    float* out = (float*)d_out;
    (void)in_sizes; (void)n_in; (void)out_size;

    float *xh, *h, *bias512;
    bf16 *xhh, *hh, *ghh, *gih, *mh, *aggh, *B0h, *B1h, *B2h;
    void* p;
    cudaGetSymbolAddress(&p, g_xh);      xh = (float*)p;
    cudaGetSymbolAddress(&p, g_xhh);     xhh = (bf16*)p;
    cudaGetSymbolAddress(&p, g_h);       h = (float*)p;
    cudaGetSymbolAddress(&p, g_hh);      hh = (bf16*)p;
    cudaGetSymbolAddress(&p, g_ghh);     ghh = (bf16*)p;
    cudaGetSymbolAddress(&p, g_gih);     gih = (bf16*)p;
    cudaGetSymbolAddress(&p, g_mh);      mh = (bf16*)p;
    cudaGetSymbolAddress(&p, g_aggh);    aggh = (bf16*)p;
    cudaGetSymbolAddress(&p, g_B0h);     B0h = (bf16*)p;
    cudaGetSymbolAddress(&p, g_B1h);     B1h = (bf16*)p;
    cudaGetSymbolAddress(&p, g_B2h);     B2h = (bf16*)p;
    cudaGetSymbolAddress(&p, g_bias512); bias512 = (float*)p;

    cudaFuncSetAttribute(gemm_bf16, cudaFuncAttributeMaxDynamicSharedMemorySize,
                         TILE_SMEM);

    // one-time stream/event setup (on the non-captured correctness call)
    static cudaStream_t s2 = nullptr, s3 = nullptr;
    static cudaEvent_t evF = nullptr, evJ = nullptr, evE = nullptr, evW = nullptr;
    if (s2 == nullptr) {
        cudaStreamCreateWithFlags(&s2, cudaStreamNonBlocking);
        cudaStreamCreateWithFlags(&s3, cudaStreamNonBlocking);
        cudaEventCreateWithFlags(&evF, cudaEventDisableTiming);
        cudaEventCreateWithFlags(&evJ, cudaEventDisableTiming);
        cudaEventCreateWithFlags(&evE, cudaEventDisableTiming);
        cudaEventCreateWithFlags(&evW, cudaEventDisableTiming);
    }

    const int NC = N_NODES * C;
    const int mtiles = (N_NODES + 127) / 128;      // 391
    const int etiles = (N_EDGES + 127) / 128;      // 4688

    // root
    detect_kernel<<<1, 64>>>((const long long*)eidx);
    cudaEventRecord(evF, 0);
    cudaStreamWaitEvent(s2, evF, 0);
    cudaStreamWaitEvent(s3, evF, 0);

    // ---- chain C (ea, edge order — depends only on inputs) on s3 ----
    prep_eW<<<8, 256, 0, s3>>>(edgeW);
    ea_gemm<<<etiles, 256, 0, s3>>>(eattr);
    cudaEventRecord(evE, s3);

    // ---- chain B (weights first, then graph/CSR) on s2 ----
    prep_weights<<<256, 256, 0, s2>>>(convW, w_ih, w_hh, b_hh);
    cudaEventRecord(evW, s2);
    zero_deg<<<(N_NODES + 255) / 256, 256, 0, s2>>>();
    normalize_edges<<<(N_EDGES + 255) / 256, 256, 0, s2>>>(eidx);
    scan_part<<<SCAN_BLOCKS, 256, 0, s2>>>();
    scan_top<<<1, 256, 0, s2>>>();
    scan_block<<<SCAN_BLOCKS, 256, 0, s2>>>();
    scatter_k<<<(N_EDGES + 255) / 256, 256, 0, s2>>>();
    cudaEventRecord(evJ, s2);

    // ---- chain A (BN + layer-0 GEMM1) on capture stream ----
    zero_bn<<<1, 128>>>();
    bn_stats<<<1024, 256>>>(x);
    bn_apply<<<(NC / 4 + 255) / 256, 256>>>(x, gamma, beta);
    cudaStreamWaitEvent(0, evW, 0);     // gemm1 needs B0h/bias512
    gemm_bf16<<<dim3(4, mtiles), 256, TILE_SMEM>>>(xhh, B0h, 512, bias512,
                                                   ghh, mh, 1, N_NODES);

    // join: agg needs CSR (B) + eah (C)
    cudaStreamWaitEvent(0, evJ, 0);
    cudaStreamWaitEvent(0, evE, 0);

    // layer 0
    agg_csr<<<(N_NODES + 7) / 8, 256>>>();
    gemm_bf16<<<dim3(3, mtiles), 256, TILE_SMEM>>>(aggh, B2h, 384, b_ih,
                                                   gih, nullptr, 0, N_NODES);
    gru_gates<<<(NC / 4 + 255) / 256, 256>>>(xh, h, hh, 0);

    // layer 1
    gemm_bf16<<<dim3(4, mtiles), 256, TILE_SMEM>>>(hh, B1h, 512, bias512,
                                                   ghh, mh, 1, N_NODES);
    agg_csr<<<(N_NODES + 7) / 8, 256>>>();
    gemm_bf16<<<dim3(3, mtiles), 256, TILE_SMEM>>>(aggh, B2h, 384, b_ih,
                                                   gih, nullptr, 0, N_NODES);
    gru_gates<<<(NC / 4 + 255) / 256, 256>>>(h, out, nullptr, 1);
}

// round 14
// speedup vs baseline: 1.6270x; 1.1846x over previous
#include <cuda_runtime.h>
#include <cuda_bf16.h>
#include <math.h>
#include <stdint.h>

#define N_NODES 50000
#define N_EDGES 600000
#define C 128
#define EC 16
#define BN_EPS 1e-5f
#define ALPHA 0.5f

typedef __nv_bfloat16 bf16;
typedef __nv_bfloat162 bf162;

// ---------------- device scratch (no allocations allowed) ----------------
__device__ float g_xh[N_NODES * C];          // BN output (x0) fp32
__device__ bf16  g_xhh[N_NODES * C];         // BN output bf16 (GEMM A)
__device__ float g_h[N_NODES * C];           // h after layer 0 (fp32)
__device__ bf16  g_hh[N_NODES * C];          // h bf16 (GEMM A, layer 1)
__device__ bf16  g_ghh[N_NODES * 384];       // gh bf16 (fp32-accumulated, demoted)
__device__ bf16  g_gih[N_NODES * 384];       // gi bf16 (fp32-accumulated, demoted)
__device__ bf16  g_mh[N_NODES * C];          // bf16 copy of m (gather source)
__device__ bf16  g_aggh[N_NODES * C];        // (agg/deg) bf16 (GEMM2 A)
__device__ bf16  g_eah[N_EDGES * C];         // ea per EDGE (edge order), bf16
__device__ int   g_src[N_EDGES];
__device__ int   g_dst[N_EDGES];
__device__ int2  g_csr[N_EDGES];             // {src, eid} per CSR position
__device__ int   g_degi[N_NODES];
__device__ int   g_ptr[N_NODES + 1];
__device__ int   g_cur[N_NODES];
__device__ int   g_bsum[256];
__device__ int   g_boff[256];
__device__ float g_invdeg[N_NODES];
__device__ float g_sum[C];
__device__ float g_sq[C];
__device__ bf16  g_B0h[512 * 128];           // [convW0^T | w_hh] rows n, k contig
__device__ bf16  g_B1h[512 * 128];           // [convW1^T | w_hh]
__device__ bf16  g_B2h[384 * 128];           // w_ih (already [384][128] k-contig)
__device__ bf16  g_eWh[128 * 16];            // edge_W^T: [n][k] bf16
__device__ float g_bias512[512];             // [0...0 | b_hh]
__device__ int   g_is64;

// ---------------- small PTX helpers ----------------
__device__ __forceinline__ uint32_t smem_u32(const void* p) {
    uint32_t a;
    asm("{ .reg .u64 t; cvta.to.shared.u64 t, %1; cvt.u32.u64 %0, t; }"
        : "=r"(a) : "l"(p));
    return a;
}
__device__ __forceinline__ void ldmx4(uint32_t* r, uint32_t addr) {
    asm volatile("ldmatrix.sync.aligned.m8n8.x4.shared.b16 {%0,%1,%2,%3}, [%4];"
        : "=r"(r[0]), "=r"(r[1]), "=r"(r[2]), "=r"(r[3]) : "r"(addr));
}
__device__ __forceinline__ void mma_bf16(float* d, const uint32_t* a,
                                         const uint32_t* b) {
    asm volatile(
        "mma.sync.aligned.m16n8k16.row.col.f32.bf16.bf16.f32 "
        "{%0,%1,%2,%3}, {%4,%5,%6,%7}, {%8,%9}, {%0,%1,%2,%3};"
        : "+f"(d[0]), "+f"(d[1]), "+f"(d[2]), "+f"(d[3])
        : "r"(a[0]), "r"(a[1]), "r"(a[2]), "r"(a[3]), "r"(b[0]), "r"(b[1]));
}
__device__ __forceinline__ float sigm(float x) { return 1.f / (1.f + expf(-x)); }
__device__ __forceinline__ uint32_t pack_bf2(float a, float b) {
    bf162 p = __float22bfloat162_rn(make_float2(a, b));
    return *(uint32_t*)&p;
}

#define STG_STRIDE 68   // uint32 per staged row (padding: banks 4r+c all distinct)

// ---------------- edge_index dtype detection ----------------
__global__ void detect_kernel(const long long* __restrict__ raw) {
    __shared__ int bad;
    if (threadIdx.x == 0) bad = 0;
    __syncthreads();
    long long v = raw[threadIdx.x];   // 64 threads
    if (v < 0 || v >= (1LL << 31)) atomicExch(&bad, 1);
    __syncthreads();
    if (threadIdx.x == 0) g_is64 = bad ? 0 : 1;
}

// normalize + degree count fused
__global__ void normalize_edges(const void* __restrict__ raw) {
    int e = blockIdx.x * blockDim.x + threadIdx.x;
    if (e >= N_EDGES) return;
    int s, d;
    if (g_is64) {
        const long long* p = (const long long*)raw;
        s = (int)p[e];
        d = (int)p[N_EDGES + e];
    } else {
        const int* p = (const int*)raw;
        s = p[e];
        d = p[N_EDGES + e];
    }
    g_src[e] = s;
    g_dst[e] = d;
    atomicAdd(&g_degi[d], 1);
}

__global__ void zero_deg() {
    int i = blockIdx.x * blockDim.x + threadIdx.x;
    if (i < N_NODES) g_degi[i] = 0;
}

__global__ void zero_bn() {
    int i = threadIdx.x;
    if (i < C) { g_sum[i] = 0.f; g_sq[i] = 0.f; }
}

#define SCAN_BLOCKS 196
__global__ void scan_part() {           // 196 x 256
    __shared__ int sh[256];
    int i = blockIdx.x * 256 + threadIdx.x;
    sh[threadIdx.x] = (i < N_NODES) ? g_degi[i] : 0;
    __syncthreads();
    for (int s = 128; s > 0; s >>= 1) {
        if (threadIdx.x < s) sh[threadIdx.x] += sh[threadIdx.x + s];
        __syncthreads();
    }
    if (threadIdx.x == 0) g_bsum[blockIdx.x] = sh[0];
}

__global__ void scan_top() {            // 1 x 256
    __shared__ int sh[256];
    int t = threadIdx.x;
    int own = (t < SCAN_BLOCKS) ? g_bsum[t] : 0;
    sh[t] = own;
    __syncthreads();
    for (int s = 1; s < 256; s <<= 1) {
        int v = (t >= s) ? sh[t - s] : 0;
        __syncthreads();
        sh[t] += v;
        __syncthreads();
    }
    if (t < SCAN_BLOCKS) g_boff[t] = sh[t] - own;   // exclusive
}

__global__ void scan_block() {          // 196 x 256, + invdeg fused
    __shared__ int sh[256];
    int t = threadIdx.x;
    int i = blockIdx.x * 256 + t;
    int v = (i < N_NODES) ? g_degi[i] : 0;
    sh[t] = v;
    __syncthreads();
    for (int s = 1; s < 256; s <<= 1) {
        int u = (t >= s) ? sh[t - s] : 0;
        __syncthreads();
        sh[t] += u;
        __syncthreads();
    }
    int excl = sh[t] - v + g_boff[blockIdx.x];
    if (i < N_NODES) {
        g_ptr[i] = excl;
        g_cur[i] = excl;
        g_invdeg[i] = 1.0f / fmaxf((float)v, 1.0f);
    }
    if (i == N_NODES - 1) g_ptr[N_NODES] = excl + v;
}

__global__ void scatter_k() {
    int e = blockIdx.x * blockDim.x + threadIdx.x;
    if (e >= N_EDGES) return;
    int s = g_src[e];
    int pos = atomicAdd(&g_cur[g_dst[e]], 1);
    g_csr[pos] = make_int2(s, e);
}

// ---------------- batchnorm (R11-verified version) ----------------
__global__ void bn_stats(const float* __restrict__ x) {
    int c = threadIdx.x & 127;
    int half = threadIdx.x >> 7;
    float s = 0.f, q = 0.f;
    int stride = gridDim.x * 8;
    for (int base = blockIdx.x * 8 + half * 4; base < N_NODES; base += stride) {
        float v0 = 0.f, v1 = 0.f, v2 = 0.f, v3 = 0.f;
        if (base + 0 < N_NODES) v0 = x[(size_t)(base + 0) * C + c];
        if (base + 1 < N_NODES) v1 = x[(size_t)(base + 1) * C + c];
        if (base + 2 < N_NODES) v2 = x[(size_t)(base + 2) * C + c];
        if (base + 3 < N_NODES) v3 = x[(size_t)(base + 3) * C + c];
        s += (v0 + v1) + (v2 + v3);
        q += (v0 * v0 + v1 * v1) + (v2 * v2 + v3 * v3);
    }
    atomicAdd(&g_sum[c], s);
    atomicAdd(&g_sq[c], q);
}

// bn_apply with bn_coef fused
__global__ void bn_apply(const float* __restrict__ x,
                         const float* __restrict__ gamma,
                         const float* __restrict__ beta) {
    int idx = blockIdx.x * blockDim.x + threadIdx.x;   // float4 index
    if (idx >= N_NODES * C / 4) return;
    int c4 = (idx & 31) * 4;
    float4 su = *(const float4*)&g_sum[c4];
    float4 sq = *(const float4*)&g_sq[c4];
    float4 gm = *(const float4*)(gamma + c4);
    float4 bt = *(const float4*)(beta + c4);
    float4 sc, sh;
#pragma unroll
    for (int j = 0; j < 4; j++) {
        float mean = (&su.x)[j] / (float)N_NODES;
        float var = (&sq.x)[j] / (float)N_NODES - mean * mean;
        float s = (&gm.x)[j] * rsqrtf(var + BN_EPS);
        (&sc.x)[j] = s;
        (&sh.x)[j] = (&bt.x)[j] - mean * s;
    }
    float4 v = *(const float4*)(x + (size_t)idx * 4);
    v.x = v.x * sc.x + sh.x;
    v.y = v.y * sc.y + sh.y;
    v.z = v.z * sc.z + sh.z;
    v.w = v.w * sc.w + sh.w;
    *(float4*)&g_xh[(size_t)idx * 4] = v;
    uint2 st;
    st.x = pack_bf2(v.x, v.y);
    st.y = pack_bf2(v.z, v.w);
    *(uint2*)&g_xhh[(size_t)idx * 4] = st;
}

// ---------------- weight prep (bf16) ----------------
__global__ void prep_eW(const float* __restrict__ eW) {
    int t = threadIdx.x + blockIdx.x * blockDim.x;
    if (t < 128 * 16) {
        int nn = t >> 4, kk = t & 15;
        g_eWh[t] = __float2bfloat16(eW[kk * 128 + nn]);
    }
}

__global__ void prep_weights(const float* __restrict__ convW,
                             const float* __restrict__ w_ih,
                             const float* __restrict__ w_hh,
                             const float* __restrict__ b_hh) {
    int idx = blockIdx.x * blockDim.x + threadIdx.x;
    int total = 512 * 128;
    for (int t = idx; t < total; t += gridDim.x * blockDim.x) {
        int n = t >> 7;
        int k = t & 127;
        float v0, v1;
        if (n < 128) {
            v0 = convW[k * 128 + n];
            v1 = convW[128 * 128 + k * 128 + n];
        } else {
            float w = w_hh[(n - 128) * 128 + k];
            v0 = w; v1 = w;
        }
        g_B0h[t] = __float2bfloat16(v0);
        g_B1h[t] = __float2bfloat16(v1);
        if (t < 384 * 128) g_B2h[t] = __float2bfloat16(w_ih[t]);
        if (t < 512) g_bias512[t] = (t < 128) ? 0.f : b_hh[t - 128];
    }
}

// ---------------- bf16 tensor-core GEMM (smem-staged STG.128 epilogue) --------
// C = A[M x 128] @ Bt^T + bias, accumulated fp32, stored bf16.
// gh_mode=1 & colBase==0 -> mcopy (m, stride 128); gh_mode=1 & colBase>0 ->
// Cmat stride 384 at (colBase-128); gh_mode=0 -> Cmat stride nb at colBase.
#define SPADH 136
#define ASH_BYTES (128 * SPADH * 2)
#define TILE_SMEM (2 * ASH_BYTES)

__global__ __launch_bounds__(256, 2)
void gemm_bf16(const bf16* __restrict__ A, const bf16* __restrict__ Bt, int nb,
               const float* __restrict__ bias, bf16* __restrict__ Cmat,
               bf16* __restrict__ mcopy, int gh_mode, int M) {
    extern __shared__ bf16 smh[];
    bf16* As = smh;                     // [128][SPADH]
    bf16* Bs = smh + 128 * SPADH;

    int tid = threadIdx.x, wid = tid >> 5, lane = tid & 31;
    int rowBase = blockIdx.y * 128, colBase = blockIdx.x * 128;
    uint32_t As_u = smem_u32(As), Bs_u = smem_u32(Bs);

#pragma unroll
    for (int i = 0; i < 8; i++) {
        int c = tid + i * 256;
        int r = c >> 4, o = c & 15;
        int grow = rowBase + r;
        uint32_t sa = As_u + r * (SPADH * 2) + o * 16;
        int gr = (grow < M) ? grow : (M - 1);
        const void* ga = A + (size_t)gr * 128 + o * 8;
        uint32_t sz = (grow < M) ? 16u : 0u;
        asm volatile("cp.async.cg.shared.global [%0], [%1], 16, %2;"
                     :: "r"(sa), "l"(ga), "r"(sz));
    }
#pragma unroll
    for (int i = 0; i < 8; i++) {
        int c = tid + i * 256;
        int r = c >> 4, o = c & 15;
        uint32_t sa = Bs_u + r * (SPADH * 2) + o * 16;
        const void* ga = Bt + (size_t)(colBase + r) * 128 + o * 8;
        asm volatile("cp.async.cg.shared.global [%0], [%1], 16;"
                     :: "r"(sa), "l"(ga));
    }
    asm volatile("cp.async.commit_group;");
    asm volatile("cp.async.wait_group 0;" ::: "memory");
    __syncthreads();

    int mBase = (wid >> 2) * 64, nBase = (wid & 3) * 32;
    int mat = lane >> 3, rin = lane & 7;

    uint32_t aAddr[4];
#pragma unroll
    for (int mi = 0; mi < 4; mi++) {
        int row = mBase + mi * 16 + (mat & 1) * 8 + rin;
        int koff = (mat >> 1) * 8;
        aAddr[mi] = As_u + row * (SPADH * 2) + koff * 2;
    }
    uint32_t bAddr[2];
#pragma unroll
    for (int j = 0; j < 2; j++) {
        int row = nBase + j * 16 + (mat >> 1) * 8 + rin;
        int koff = (mat & 1) * 8;
        bAddr[j] = Bs_u + row * (SPADH * 2) + koff * 2;
    }

    float acc[4][4][4] = {};
#pragma unroll
    for (int ks = 0; ks < 8; ks++) {
        uint32_t afr[4][4], bfr[2][4];
#pragma unroll
        for (int mi = 0; mi < 4; mi++) ldmx4(afr[mi], aAddr[mi] + ks * 32);
#pragma unroll
        for (int j = 0; j < 2; j++) ldmx4(bfr[j], bAddr[j] + ks * 32);
#pragma unroll
        for (int mi = 0; mi < 4; mi++) {
            mma_bf16(acc[mi][0], afr[mi], &bfr[0][0]);
            mma_bf16(acc[mi][1], afr[mi], &bfr[0][2]);
            mma_bf16(acc[mi][2], afr[mi], &bfr[1][0]);
            mma_bf16(acc[mi][3], afr[mi], &bfr[1][2]);
        }
    }

    // ---- stage bf162 results into smem (reuse As region), then STG.128 ----
    uint32_t* stage = (uint32_t*)smh;   // [128][STG_STRIDE]
    int qr = lane >> 2, qc = lane & 3;
    __syncthreads();                    // all smem reads (ldmatrix) complete
#pragma unroll
    for (int mi = 0; mi < 4; mi++) {
        int rl = mBase + mi * 16 + qr;
#pragma unroll
        for (int ni = 0; ni < 4; ni++) {
            int ccl = nBase + ni * 8 + qc * 2;
            float2 bv = *(const float2*)(bias + colBase + ccl);
            stage[rl * STG_STRIDE + (ccl >> 1)] =
                pack_bf2(acc[mi][ni][0] + bv.x, acc[mi][ni][1] + bv.y);
            stage[(rl + 8) * STG_STRIDE + (ccl >> 1)] =
                pack_bf2(acc[mi][ni][2] + bv.x, acc[mi][ni][3] + bv.y);
        }
    }
    __syncthreads();

    // destination base (uniform per block)
    bf16* dstBase;
    int dstStride;
    if (gh_mode) {
        if (colBase == 0) { dstBase = mcopy; dstStride = 128; }
        else { dstBase = Cmat + (colBase - 128); dstStride = 384; }
    } else {
        dstBase = Cmat + colBase;
        dstStride = nb;
    }
#pragma unroll
    for (int i = 0; i < 8; i++) {
        int cidx = tid + i * 256;
        int r = cidx >> 4, o = cidx & 15;     // 16 uint4 per 128-col row
        int grow = rowBase + r;
        if (grow < M) {
            uint4 v = *(uint4*)&stage[r * STG_STRIDE + o * 4];
            *((uint4*)(dstBase + (size_t)grow * dstStride) + o) = v;
        }
    }
}

// ---------------- ea GEMM (smem-staged epilogue), EDGE order -------------------
#define SPADE 24
__global__ __launch_bounds__(256, 4)
void ea_gemm(const float* __restrict__ eattr) {
    __shared__ bf16 As[128 * SPADE];
    __shared__ bf16 Bs[128 * SPADE];
    __shared__ uint32_t stage[128 * STG_STRIDE];

    int tid = threadIdx.x, wid = tid >> 5, lane = tid & 31;
    int rowBase = blockIdx.x * 128;
    uint32_t As_u = smem_u32(As), Bs_u = smem_u32(Bs);

    {
        int r = tid >> 1, part = tid & 1;
        int p = rowBase + r;
        int row = (p < N_EDGES) ? p : (N_EDGES - 1);
        const float4* src = (const float4*)(eattr + (size_t)row * 16 + part * 8);
        float4 v0 = src[0], v1 = src[1];
        uint4 st;
        st.x = pack_bf2(v0.x, v0.y);
        st.y = pack_bf2(v0.z, v0.w);
        st.z = pack_bf2(v1.x, v1.y);
        st.w = pack_bf2(v1.z, v1.w);
        *(uint4*)&As[r * SPADE + part * 8] = st;
    }
    {
        int r = tid >> 1, part = tid & 1;
        uint4 v = *(const uint4*)&g_eWh[r * 16 + part * 8];
        *(uint4*)&Bs[r * SPADE + part * 8] = v;
    }
    __syncthreads();

    int mBase = (wid >> 2) * 64, nBase = (wid & 3) * 32;
    int mat = lane >> 3, rin = lane & 7;

    uint32_t afr[4][4], bfr[2][4];
#pragma unroll
    for (int mi = 0; mi < 4; mi++) {
        int row = mBase + mi * 16 + (mat & 1) * 8 + rin;
        int koff = (mat >> 1) * 8;
        ldmx4(afr[mi], As_u + row * (SPADE * 2) + koff * 2);
    }
#pragma unroll
    for (int j = 0; j < 2; j++) {
        int row = nBase + j * 16 + (mat >> 1) * 8 + rin;
        int koff = (mat & 1) * 8;
        ldmx4(bfr[j], Bs_u + row * (SPADE * 2) + koff * 2);
    }

    float acc[4][4][4] = {};
#pragma unroll
    for (int mi = 0; mi < 4; mi++) {
        mma_bf16(acc[mi][0], afr[mi], &bfr[0][0]);
        mma_bf16(acc[mi][1], afr[mi], &bfr[0][2]);
        mma_bf16(acc[mi][2], afr[mi], &bfr[1][0]);
        mma_bf16(acc[mi][3], afr[mi], &bfr[1][2]);
    }

    int qr = lane >> 2, qc = lane & 3;
#pragma unroll
    for (int mi = 0; mi < 4; mi++) {
        int rl = mBase + mi * 16 + qr;
#pragma unroll
        for (int ni = 0; ni < 4; ni++) {
            int ccl = nBase + ni * 8 + qc * 2;
            stage[rl * STG_STRIDE + (ccl >> 1)] =
                pack_bf2(acc[mi][ni][0], acc[mi][ni][1]);
            stage[(rl + 8) * STG_STRIDE + (ccl >> 1)] =
                pack_bf2(acc[mi][ni][2], acc[mi][ni][3]);
        }
    }
    __syncthreads();

#pragma unroll
    for (int i = 0; i < 8; i++) {
        int cidx = tid + i * 256;
        int r = cidx >> 4, o = cidx & 15;
        int grow = rowBase + r;
        if (grow < N_EDGES) {
            uint4 v = *(uint4*)&stage[r * STG_STRIDE + o * 4];
            *((uint4*)(g_eah + (size_t)grow * 128) + o) = v;
        }
    }
}

// ---------------- CSR aggregation: one warp per node ----------------
__global__ void agg_csr() {
    int warp = (blockIdx.x * blockDim.x + threadIdx.x) >> 5;
    int lane = threadIdx.x & 31;
    if (warp >= N_NODES) return;

    int beg = g_ptr[warp], end = g_ptr[warp + 1];
    float4 acc = make_float4(0.f, 0.f, 0.f, 0.f);

    for (int e = beg; e < end; e++) {
        int2 se = g_csr[e];
        uint2 ev = *(const uint2*)&g_eah[(size_t)se.y * C + lane * 4];
        uint2 mv = *(const uint2*)&g_mh[(size_t)se.x * C + lane * 4];
        float2 e01 = __bfloat1622float2(*(bf162*)&ev.x);
        float2 e23 = __bfloat1622float2(*(bf162*)&ev.y);
        float2 m01 = __bfloat1622float2(*(bf162*)&mv.x);
        float2 m23 = __bfloat1622float2(*(bf162*)&mv.y);
        acc.x += fmaxf(m01.x + e01.x, 0.f);
        acc.y += fmaxf(m01.y + e01.y, 0.f);
        acc.z += fmaxf(m23.x + e23.x, 0.f);
        acc.w += fmaxf(m23.y + e23.y, 0.f);
    }
    float sc = g_invdeg[warp];
    uint2 st;
    st.x = pack_bf2(acc.x * sc, acc.y * sc);
    st.y = pack_bf2(acc.z * sc, acc.w * sc);
    *(uint2*)&g_aggh[(size_t)warp * C + lane * 4] = st;
}

// ---------------- GRU gates (bf16 gi/gh in, fp32 math) ----------------
__global__ void gru_gates(const float* __restrict__ hin,
                          float* __restrict__ hout, bf16* __restrict__ houth,
                          int last) {
    int idx = blockIdx.x * blockDim.x + threadIdx.x;   // 4-elem chunk index
    if (idx >= N_NODES * C / 4) return;
    int n = idx >> 5;
    int c4 = (idx & 31) * 4;
    const bf16* gib = g_gih + (size_t)n * 384;
    const bf16* ghb = g_ghh + (size_t)n * 384;

    uint2 u_ir = *(const uint2*)(gib + c4);
    uint2 u_iz = *(const uint2*)(gib + 128 + c4);
    uint2 u_in = *(const uint2*)(gib + 256 + c4);
    uint2 u_hr = *(const uint2*)(ghb + c4);
    uint2 u_hz = *(const uint2*)(ghb + 128 + c4);
    uint2 u_hn = *(const uint2*)(ghb + 256 + c4);
    float4 hv = *(const float4*)(hin + (size_t)idx * 4);

    float ir[4], iz[4], in_[4], hr[4], hz[4], hn[4];
    {
        float2 a, b;
        a = __bfloat1622float2(*(bf162*)&u_ir.x); b = __bfloat1622float2(*(bf162*)&u_ir.y);
        ir[0] = a.x; ir[1] = a.y; ir[2] = b.x; ir[3] = b.y;
        a = __bfloat1622float2(*(bf162*)&u_iz.x); b = __bfloat1622float2(*(bf162*)&u_iz.y);
        iz[0] = a.x; iz[1] = a.y; iz[2] = b.x; iz[3] = b.y;
        a = __bfloat1622float2(*(bf162*)&u_in.x); b = __bfloat1622float2(*(bf162*)&u_in.y);
        in_[0] = a.x; in_[1] = a.y; in_[2] = b.x; in_[3] = b.y;
        a = __bfloat1622float2(*(bf162*)&u_hr.x); b = __bfloat1622float2(*(bf162*)&u_hr.y);
        hr[0] = a.x; hr[1] = a.y; hr[2] = b.x; hr[3] = b.y;
        a = __bfloat1622float2(*(bf162*)&u_hz.x); b = __bfloat1622float2(*(bf162*)&u_hz.y);
        hz[0] = a.x; hz[1] = a.y; hz[2] = b.x; hz[3] = b.y;
        a = __bfloat1622float2(*(bf162*)&u_hn.x); b = __bfloat1622float2(*(bf162*)&u_hn.y);
        hn[0] = a.x; hn[1] = a.y; hn[2] = b.x; hn[3] = b.y;
    }

    float4 o;
#pragma unroll
    for (int j = 0; j < 4; j++) {
        float hj = (&hv.x)[j];
        float r = sigm(ir[j] + hr[j]);
        float z = sigm(iz[j] + hz[j]);
        float nn = tanhf(in_[j] + r * hn[j]);
        (&o.x)[j] = (1.f - z) * nn + z * hj;
    }

    if (last) {
        float4 xv = *(const float4*)(g_xh + (size_t)idx * 4);
        o.x = 0.5f * fmaxf(o.x, 0.f) + 0.5f * xv.x;
        o.y = 0.5f * fmaxf(o.y, 0.f) + 0.5f * xv.y;
        o.z = 0.5f * fmaxf(o.z, 0.f) + 0.5f * xv.z;
        o.w = 0.5f * fmaxf(o.w, 0.f) + 0.5f * xv.w;
        *(float4*)(hout + (size_t)idx * 4) = o;
    } else {
        *(float4*)(hout + (size_t)idx * 4) = o;
        uint2 st;
        st.x = pack_bf2(o.x, o.y);
        st.y = pack_bf2(o.z, o.w);
        *(uint2*)&houth[(size_t)idx * 4] = st;
    }
}

// ---------------- host ----------------
extern "C" void kernel_launch(void* const* d_in, const int* in_sizes, int n_in,
                              void* d_out, int out_size) {
    const float* x     = (const float*)d_in[0];
    const void*  eidx  = d_in[1];
    const float* eattr = (const float*)d_in[2];
    const float* gamma = (const float*)d_in[3];
    const float* beta  = (const float*)d_in[4];
    const float* edgeW = (const float*)d_in[5];
    const float* convW = (const float*)d_in[6];
    const float* w_ih  = (const float*)d_in[7];
    const float* w_hh  = (const float*)d_in[8];
    const float* b_ih  = (const float*)d_in[9];
    const float* b_hh  = (const float*)d_in[10];
    float* out = (float*)d_out;
    (void)in_sizes; (void)n_in; (void)out_size;

    float *xh, *h, *bias512;
    bf16 *xhh, *hh, *ghh, *gih, *mh, *aggh, *B0h, *B1h, *B2h;
    void* p;
    cudaGetSymbolAddress(&p, g_xh);      xh = (float*)p;
    cudaGetSymbolAddress(&p, g_xhh);     xhh = (bf16*)p;
    cudaGetSymbolAddress(&p, g_h);       h = (float*)p;
    cudaGetSymbolAddress(&p, g_hh);      hh = (bf16*)p;
    cudaGetSymbolAddress(&p, g_ghh);     ghh = (bf16*)p;
    cudaGetSymbolAddress(&p, g_gih);     gih = (bf16*)p;
    cudaGetSymbolAddress(&p, g_mh);      mh = (bf16*)p;
    cudaGetSymbolAddress(&p, g_aggh);    aggh = (bf16*)p;
    cudaGetSymbolAddress(&p, g_B0h);     B0h = (bf16*)p;
    cudaGetSymbolAddress(&p, g_B1h);     B1h = (bf16*)p;
    cudaGetSymbolAddress(&p, g_B2h);     B2h = (bf16*)p;
    cudaGetSymbolAddress(&p, g_bias512); bias512 = (float*)p;

    cudaFuncSetAttribute(gemm_bf16, cudaFuncAttributeMaxDynamicSharedMemorySize,
                         TILE_SMEM);

    // one-time stream/event setup (on the non-captured correctness call)
    static cudaStream_t s2 = nullptr, s3 = nullptr;
    static cudaEvent_t evF = nullptr, evJ = nullptr, evE = nullptr, evW = nullptr;
    if (s2 == nullptr) {
        cudaStreamCreateWithFlags(&s2, cudaStreamNonBlocking);
        cudaStreamCreateWithFlags(&s3, cudaStreamNonBlocking);
        cudaEventCreateWithFlags(&evF, cudaEventDisableTiming);
        cudaEventCreateWithFlags(&evJ, cudaEventDisableTiming);
        cudaEventCreateWithFlags(&evE, cudaEventDisableTiming);
        cudaEventCreateWithFlags(&evW, cudaEventDisableTiming);
    }

    const int NC = N_NODES * C;
    const int mtiles = (N_NODES + 127) / 128;      // 391
    const int etiles = (N_EDGES + 127) / 128;      // 4688

    // root
    detect_kernel<<<1, 64>>>((const long long*)eidx);
    cudaEventRecord(evF, 0);
    cudaStreamWaitEvent(s2, evF, 0);
    cudaStreamWaitEvent(s3, evF, 0);

    // ---- chain C (ea, edge order — depends only on inputs) on s3 ----
    prep_eW<<<8, 256, 0, s3>>>(edgeW);
    ea_gemm<<<etiles, 256, 0, s3>>>(eattr);
    cudaEventRecord(evE, s3);

    // ---- chain B (weights first, then graph/CSR) on s2 ----
    prep_weights<<<256, 256, 0, s2>>>(convW, w_ih, w_hh, b_hh);
    cudaEventRecord(evW, s2);
    zero_deg<<<(N_NODES + 255) / 256, 256, 0, s2>>>();
    normalize_edges<<<(N_EDGES + 255) / 256, 256, 0, s2>>>(eidx);
    scan_part<<<SCAN_BLOCKS, 256, 0, s2>>>();
    scan_top<<<1, 256, 0, s2>>>();
    scan_block<<<SCAN_BLOCKS, 256, 0, s2>>>();
    scatter_k<<<(N_EDGES + 255) / 256, 256, 0, s2>>>();
    cudaEventRecord(evJ, s2);

    // ---- chain A (BN + layer-0 GEMM1) on capture stream ----
    zero_bn<<<1, 128>>>();
    bn_stats<<<1024, 256>>>(x);
    bn_apply<<<(NC / 4 + 255) / 256, 256>>>(x, gamma, beta);
    cudaStreamWaitEvent(0, evW, 0);     // gemm1 needs B0h/bias512
    gemm_bf16<<<dim3(4, mtiles), 256, TILE_SMEM>>>(xhh, B0h, 512, bias512,
                                                   ghh, mh, 1, N_NODES);

    // join: agg needs CSR (B) + eah (C)
    cudaStreamWaitEvent(0, evJ, 0);
    cudaStreamWaitEvent(0, evE, 0);

    // layer 0
    agg_csr<<<(N_NODES + 7) / 8, 256>>>();
    gemm_bf16<<<dim3(3, mtiles), 256, TILE_SMEM>>>(aggh, B2h, 384, b_ih,
                                                   gih, nullptr, 0, N_NODES);
    gru_gates<<<(NC / 4 + 255) / 256, 256>>>(xh, h, hh, 0);

    // layer 1
    gemm_bf16<<<dim3(4, mtiles), 256, TILE_SMEM>>>(hh, B1h, 512, bias512,
                                                   ghh, mh, 1, N_NODES);
    agg_csr<<<(N_NODES + 7) / 8, 256>>>();
    gemm_bf16<<<dim3(3, mtiles), 256, TILE_SMEM>>>(aggh, B2h, 384, b_ih,
                                                   gih, nullptr, 0, N_NODES);
    gru_gates<<<(NC / 4 + 255) / 256, 256>>>(h, out, nullptr, 1);
}

// round 15
// speedup vs baseline: 1.6583x; 1.0192x over previous
#include <cuda_runtime.h>
#include <cuda_bf16.h>
#include <math.h>
#include <stdint.h>

#define N_NODES 50000
#define N_EDGES 600000
#define C 128
#define EC 16
#define BN_EPS 1e-5f
#define ALPHA 0.5f

typedef __nv_bfloat16 bf16;
typedef __nv_bfloat162 bf162;

// ---------------- device scratch (no allocations allowed) ----------------
__device__ float g_xh[N_NODES * C];          // BN output (x0) fp32
__device__ bf16  g_xhh[N_NODES * C];         // BN output bf16 (GEMM A)
__device__ float g_h[N_NODES * C];           // h after layer 0 (fp32)
__device__ bf16  g_hh[N_NODES * C];          // h bf16 (GEMM A, layer 1)
__device__ bf16  g_ghh[N_NODES * 384];       // gh bf16 (fp32-accumulated, demoted)
__device__ bf16  g_gih[N_NODES * 384];       // gi bf16 (fp32-accumulated, demoted)
__device__ bf16  g_mh[N_NODES * C];          // bf16 copy of m (gather source)
__device__ bf16  g_aggh[N_NODES * C];        // (agg/deg) bf16 (GEMM2 A)
__device__ bf16  g_eah[N_EDGES * C];         // ea per EDGE (edge order), bf16
__device__ int   g_src[N_EDGES];
__device__ int   g_dst[N_EDGES];
__device__ int2  g_csr[N_EDGES];             // {src, eid} per CSR position
__device__ int   g_degi[N_NODES];
__device__ int   g_ptr[N_NODES + 1];
__device__ int   g_cur[N_NODES];
__device__ int   g_bsum[256];
__device__ int   g_boff[256];
__device__ float g_invdeg[N_NODES];
__device__ float g_sum[C];
__device__ float g_sq[C];
__device__ bf16  g_B0h[512 * 128];           // [convW0^T | w_hh] rows n, k contig
__device__ bf16  g_B1h[512 * 128];           // [convW1^T | w_hh]
__device__ bf16  g_B2h[384 * 128];           // w_ih (already [384][128] k-contig)
__device__ bf16  g_eWh[128 * 16];            // edge_W^T: [n][k] bf16
__device__ float g_bias512[512];             // [0...0 | b_hh]
__device__ int   g_is64;

// ---------------- small PTX helpers ----------------
__device__ __forceinline__ uint32_t smem_u32(const void* p) {
    uint32_t a;
    asm("{ .reg .u64 t; cvta.to.shared.u64 t, %1; cvt.u32.u64 %0, t; }"
        : "=r"(a) : "l"(p));
    return a;
}
__device__ __forceinline__ void ldmx4(uint32_t* r, uint32_t addr) {
    asm volatile("ldmatrix.sync.aligned.m8n8.x4.shared.b16 {%0,%1,%2,%3}, [%4];"
        : "=r"(r[0]), "=r"(r[1]), "=r"(r[2]), "=r"(r[3]) : "r"(addr));
}
__device__ __forceinline__ void mma_bf16(float* d, const uint32_t* a,
                                         const uint32_t* b) {
    asm volatile(
        "mma.sync.aligned.m16n8k16.row.col.f32.bf16.bf16.f32 "
        "{%0,%1,%2,%3}, {%4,%5,%6,%7}, {%8,%9}, {%0,%1,%2,%3};"
        : "+f"(d[0]), "+f"(d[1]), "+f"(d[2]), "+f"(d[3])
        : "r"(a[0]), "r"(a[1]), "r"(a[2]), "r"(a[3]), "r"(b[0]), "r"(b[1]));
}
__device__ __forceinline__ float sigm(float x) { return 1.f / (1.f + expf(-x)); }
__device__ __forceinline__ uint32_t pack_bf2(float a, float b) {
    bf162 p = __float22bfloat162_rn(make_float2(a, b));
    return *(uint32_t*)&p;
}

#define STG_STRIDE 68   // uint32 per staged row (padding: banks 4r+c all distinct)

// ---------------- edge_index dtype detection ----------------
__global__ void detect_kernel(const long long* __restrict__ raw) {
    __shared__ int bad;
    if (threadIdx.x == 0) bad = 0;
    __syncthreads();
    long long v = raw[threadIdx.x];   // 64 threads
    if (v < 0 || v >= (1LL << 31)) atomicExch(&bad, 1);
    __syncthreads();
    if (threadIdx.x == 0) g_is64 = bad ? 0 : 1;
}

// normalize + degree count fused
__global__ void normalize_edges(const void* __restrict__ raw) {
    int e = blockIdx.x * blockDim.x + threadIdx.x;
    if (e >= N_EDGES) return;
    int s, d;
    if (g_is64) {
        const long long* p = (const long long*)raw;
        s = (int)p[e];
        d = (int)p[N_EDGES + e];
    } else {
        const int* p = (const int*)raw;
        s = p[e];
        d = p[N_EDGES + e];
    }
    g_src[e] = s;
    g_dst[e] = d;
    atomicAdd(&g_degi[d], 1);
}

__global__ void zero_deg() {
    int i = blockIdx.x * blockDim.x + threadIdx.x;
    if (i < N_NODES) g_degi[i] = 0;
}

__global__ void zero_bn() {
    int i = threadIdx.x;
    if (i < C) { g_sum[i] = 0.f; g_sq[i] = 0.f; }
}

#define SCAN_BLOCKS 196
__global__ void scan_part() {           // 196 x 256
    __shared__ int sh[256];
    int i = blockIdx.x * 256 + threadIdx.x;
    sh[threadIdx.x] = (i < N_NODES) ? g_degi[i] : 0;
    __syncthreads();
    for (int s = 128; s > 0; s >>= 1) {
        if (threadIdx.x < s) sh[threadIdx.x] += sh[threadIdx.x + s];
        __syncthreads();
    }
    if (threadIdx.x == 0) g_bsum[blockIdx.x] = sh[0];
}

__global__ void scan_top() {            // 1 x 256
    __shared__ int sh[256];
    int t = threadIdx.x;
    int own = (t < SCAN_BLOCKS) ? g_bsum[t] : 0;
    sh[t] = own;
    __syncthreads();
    for (int s = 1; s < 256; s <<= 1) {
        int v = (t >= s) ? sh[t - s] : 0;
        __syncthreads();
        sh[t] += v;
        __syncthreads();
    }
    if (t < SCAN_BLOCKS) g_boff[t] = sh[t] - own;   // exclusive
}

__global__ void scan_block() {          // 196 x 256, + invdeg fused
    __shared__ int sh[256];
    int t = threadIdx.x;
    int i = blockIdx.x * 256 + t;
    int v = (i < N_NODES) ? g_degi[i] : 0;
    sh[t] = v;
    __syncthreads();
    for (int s = 1; s < 256; s <<= 1) {
        int u = (t >= s) ? sh[t - s] : 0;
        __syncthreads();
        sh[t] += u;
        __syncthreads();
    }
    int excl = sh[t] - v + g_boff[blockIdx.x];
    if (i < N_NODES) {
        g_ptr[i] = excl;
        g_cur[i] = excl;
        g_invdeg[i] = 1.0f / fmaxf((float)v, 1.0f);
    }
    if (i == N_NODES - 1) g_ptr[N_NODES] = excl + v;
}

__global__ void scatter_k() {
    int e = blockIdx.x * blockDim.x + threadIdx.x;
    if (e >= N_EDGES) return;
    int s = g_src[e];
    int pos = atomicAdd(&g_cur[g_dst[e]], 1);
    g_csr[pos] = make_int2(s, e);
}

// ---------------- batchnorm (R11-verified version) ----------------
__global__ void bn_stats(const float* __restrict__ x) {
    int c = threadIdx.x & 127;
    int half = threadIdx.x >> 7;
    float s = 0.f, q = 0.f;
    int stride = gridDim.x * 8;
    for (int base = blockIdx.x * 8 + half * 4; base < N_NODES; base += stride) {
        float v0 = 0.f, v1 = 0.f, v2 = 0.f, v3 = 0.f;
        if (base + 0 < N_NODES) v0 = x[(size_t)(base + 0) * C + c];
        if (base + 1 < N_NODES) v1 = x[(size_t)(base + 1) * C + c];
        if (base + 2 < N_NODES) v2 = x[(size_t)(base + 2) * C + c];
        if (base + 3 < N_NODES) v3 = x[(size_t)(base + 3) * C + c];
        s += (v0 + v1) + (v2 + v3);
        q += (v0 * v0 + v1 * v1) + (v2 * v2 + v3 * v3);
    }
    atomicAdd(&g_sum[c], s);
    atomicAdd(&g_sq[c], q);
}

// bn_apply with bn_coef fused
__global__ void bn_apply(const float* __restrict__ x,
                         const float* __restrict__ gamma,
                         const float* __restrict__ beta) {
    int idx = blockIdx.x * blockDim.x + threadIdx.x;   // float4 index
    if (idx >= N_NODES * C / 4) return;
    int c4 = (idx & 31) * 4;
    float4 su = *(const float4*)&g_sum[c4];
    float4 sq = *(const float4*)&g_sq[c4];
    float4 gm = *(const float4*)(gamma + c4);
    float4 bt = *(const float4*)(beta + c4);
    float4 sc, sh;
#pragma unroll
    for (int j = 0; j < 4; j++) {
        float mean = (&su.x)[j] / (float)N_NODES;
        float var = (&sq.x)[j] / (float)N_NODES - mean * mean;
        float s = (&gm.x)[j] * rsqrtf(var + BN_EPS);
        (&sc.x)[j] = s;
        (&sh.x)[j] = (&bt.x)[j] - mean * s;
    }
    float4 v = *(const float4*)(x + (size_t)idx * 4);
    v.x = v.x * sc.x + sh.x;
    v.y = v.y * sc.y + sh.y;
    v.z = v.z * sc.z + sh.z;
    v.w = v.w * sc.w + sh.w;
    *(float4*)&g_xh[(size_t)idx * 4] = v;
    uint2 st;
    st.x = pack_bf2(v.x, v.y);
    st.y = pack_bf2(v.z, v.w);
    *(uint2*)&g_xhh[(size_t)idx * 4] = st;
}

// ---------------- weight prep (bf16) ----------------
__global__ void prep_eW(const float* __restrict__ eW) {
    int t = threadIdx.x + blockIdx.x * blockDim.x;
    if (t < 128 * 16) {
        int nn = t >> 4, kk = t & 15;
        g_eWh[t] = __float2bfloat16(eW[kk * 128 + nn]);
    }
}

__global__ void prep_weights(const float* __restrict__ convW,
                             const float* __restrict__ w_ih,
                             const float* __restrict__ w_hh,
                             const float* __restrict__ b_hh) {
    int idx = blockIdx.x * blockDim.x + threadIdx.x;
    int total = 512 * 128;
    for (int t = idx; t < total; t += gridDim.x * blockDim.x) {
        int n = t >> 7;
        int k = t & 127;
        float v0, v1;
        if (n < 128) {
            v0 = convW[k * 128 + n];
            v1 = convW[128 * 128 + k * 128 + n];
        } else {
            float w = w_hh[(n - 128) * 128 + k];
            v0 = w; v1 = w;
        }
        g_B0h[t] = __float2bfloat16(v0);
        g_B1h[t] = __float2bfloat16(v1);
        if (t < 384 * 128) g_B2h[t] = __float2bfloat16(w_ih[t]);
        if (t < 512) g_bias512[t] = (t < 128) ? 0.f : b_hh[t - 128];
    }
}

// ---------------- bf16 tensor-core GEMM (smem-staged STG.128 epilogue) --------
#define SPADH 136
#define ASH_BYTES (128 * SPADH * 2)
#define TILE_SMEM (2 * ASH_BYTES)

__global__ __launch_bounds__(256, 2)
void gemm_bf16(const bf16* __restrict__ A, const bf16* __restrict__ Bt, int nb,
               const float* __restrict__ bias, bf16* __restrict__ Cmat,
               bf16* __restrict__ mcopy, int gh_mode, int M) {
    extern __shared__ bf16 smh[];
    bf16* As = smh;                     // [128][SPADH]
    bf16* Bs = smh + 128 * SPADH;

    int tid = threadIdx.x, wid = tid >> 5, lane = tid & 31;
    int rowBase = blockIdx.y * 128, colBase = blockIdx.x * 128;
    uint32_t As_u = smem_u32(As), Bs_u = smem_u32(Bs);

#pragma unroll
    for (int i = 0; i < 8; i++) {
        int c = tid + i * 256;
        int r = c >> 4, o = c & 15;
        int grow = rowBase + r;
        uint32_t sa = As_u + r * (SPADH * 2) + o * 16;
        int gr = (grow < M) ? grow : (M - 1);
        const void* ga = A + (size_t)gr * 128 + o * 8;
        uint32_t sz = (grow < M) ? 16u : 0u;
        asm volatile("cp.async.cg.shared.global [%0], [%1], 16, %2;"
                     :: "r"(sa), "l"(ga), "r"(sz));
    }
#pragma unroll
    for (int i = 0; i < 8; i++) {
        int c = tid + i * 256;
        int r = c >> 4, o = c & 15;
        uint32_t sa = Bs_u + r * (SPADH * 2) + o * 16;
        const void* ga = Bt + (size_t)(colBase + r) * 128 + o * 8;
        asm volatile("cp.async.cg.shared.global [%0], [%1], 16;"
                     :: "r"(sa), "l"(ga));
    }
    asm volatile("cp.async.commit_group;");
    asm volatile("cp.async.wait_group 0;" ::: "memory");
    __syncthreads();

    int mBase = (wid >> 2) * 64, nBase = (wid & 3) * 32;
    int mat = lane >> 3, rin = lane & 7;

    uint32_t aAddr[4];
#pragma unroll
    for (int mi = 0; mi < 4; mi++) {
        int row = mBase + mi * 16 + (mat & 1) * 8 + rin;
        int koff = (mat >> 1) * 8;
        aAddr[mi] = As_u + row * (SPADH * 2) + koff * 2;
    }
    uint32_t bAddr[2];
#pragma unroll
    for (int j = 0; j < 2; j++) {
        int row = nBase + j * 16 + (mat >> 1) * 8 + rin;
        int koff = (mat & 1) * 8;
        bAddr[j] = Bs_u + row * (SPADH * 2) + koff * 2;
    }

    float acc[4][4][4] = {};
#pragma unroll
    for (int ks = 0; ks < 8; ks++) {
        uint32_t afr[4][4], bfr[2][4];
#pragma unroll
        for (int mi = 0; mi < 4; mi++) ldmx4(afr[mi], aAddr[mi] + ks * 32);
#pragma unroll
        for (int j = 0; j < 2; j++) ldmx4(bfr[j], bAddr[j] + ks * 32);
#pragma unroll
        for (int mi = 0; mi < 4; mi++) {
            mma_bf16(acc[mi][0], afr[mi], &bfr[0][0]);
            mma_bf16(acc[mi][1], afr[mi], &bfr[0][2]);
            mma_bf16(acc[mi][2], afr[mi], &bfr[1][0]);
            mma_bf16(acc[mi][3], afr[mi], &bfr[1][2]);
        }
    }

    // ---- stage bf162 results into smem (reuse As region), then STG.128 ----
    uint32_t* stage = (uint32_t*)smh;   // [128][STG_STRIDE]
    int qr = lane >> 2, qc = lane & 3;
    __syncthreads();                    // all smem reads (ldmatrix) complete
#pragma unroll
    for (int mi = 0; mi < 4; mi++) {
        int rl = mBase + mi * 16 + qr;
#pragma unroll
        for (int ni = 0; ni < 4; ni++) {
            int ccl = nBase + ni * 8 + qc * 2;
            float2 bv = *(const float2*)(bias + colBase + ccl);
            stage[rl * STG_STRIDE + (ccl >> 1)] =
                pack_bf2(acc[mi][ni][0] + bv.x, acc[mi][ni][1] + bv.y);
            stage[(rl + 8) * STG_STRIDE + (ccl >> 1)] =
                pack_bf2(acc[mi][ni][2] + bv.x, acc[mi][ni][3] + bv.y);
        }
    }
    __syncthreads();

    // destination base (uniform per block)
    bf16* dstBase;
    int dstStride;
    if (gh_mode) {
        if (colBase == 0) { dstBase = mcopy; dstStride = 128; }
        else { dstBase = Cmat + (colBase - 128); dstStride = 384; }
    } else {
        dstBase = Cmat + colBase;
        dstStride = nb;
    }
#pragma unroll
    for (int i = 0; i < 8; i++) {
        int cidx = tid + i * 256;
        int r = cidx >> 4, o = cidx & 15;     // 16 uint4 per 128-col row
        int grow = rowBase + r;
        if (grow < M) {
            uint4 v = *(uint4*)&stage[r * STG_STRIDE + o * 4];
            *((uint4*)(dstBase + (size_t)grow * dstStride) + o) = v;
        }
    }
}

// ---------------- ea GEMM (smem-staged epilogue), EDGE order -------------------
#define SPADE 24
__global__ __launch_bounds__(256, 4)
void ea_gemm(const float* __restrict__ eattr) {
    __shared__ bf16 As[128 * SPADE];
    __shared__ bf16 Bs[128 * SPADE];
    __shared__ uint32_t stage[128 * STG_STRIDE];

    int tid = threadIdx.x, wid = tid >> 5, lane = tid & 31;
    int rowBase = blockIdx.x * 128;
    uint32_t As_u = smem_u32(As), Bs_u = smem_u32(Bs);

    {
        int r = tid >> 1, part = tid & 1;
        int p = rowBase + r;
        int row = (p < N_EDGES) ? p : (N_EDGES - 1);
        const float4* src = (const float4*)(eattr + (size_t)row * 16 + part * 8);
        float4 v0 = src[0], v1 = src[1];
        uint4 st;
        st.x = pack_bf2(v0.x, v0.y);
        st.y = pack_bf2(v0.z, v0.w);
        st.z = pack_bf2(v1.x, v1.y);
        st.w = pack_bf2(v1.z, v1.w);
        *(uint4*)&As[r * SPADE + part * 8] = st;
    }
    {
        int r = tid >> 1, part = tid & 1;
        uint4 v = *(const uint4*)&g_eWh[r * 16 + part * 8];
        *(uint4*)&Bs[r * SPADE + part * 8] = v;
    }
    __syncthreads();

    int mBase = (wid >> 2) * 64, nBase = (wid & 3) * 32;
    int mat = lane >> 3, rin = lane & 7;

    uint32_t afr[4][4], bfr[2][4];
#pragma unroll
    for (int mi = 0; mi < 4; mi++) {
        int row = mBase + mi * 16 + (mat & 1) * 8 + rin;
        int koff = (mat >> 1) * 8;
        ldmx4(afr[mi], As_u + row * (SPADE * 2) + koff * 2);
    }
#pragma unroll
    for (int j = 0; j < 2; j++) {
        int row = nBase + j * 16 + (mat >> 1) * 8 + rin;
        int koff = (mat & 1) * 8;
        ldmx4(bfr[j], Bs_u + row * (SPADE * 2) + koff * 2);
    }

    float acc[4][4][4] = {};
#pragma unroll
    for (int mi = 0; mi < 4; mi++) {
        mma_bf16(acc[mi][0], afr[mi], &bfr[0][0]);
        mma_bf16(acc[mi][1], afr[mi], &bfr[0][2]);
        mma_bf16(acc[mi][2], afr[mi], &bfr[1][0]);
        mma_bf16(acc[mi][3], afr[mi], &bfr[1][2]);
    }

    int qr = lane >> 2, qc = lane & 3;
#pragma unroll
    for (int mi = 0; mi < 4; mi++) {
        int rl = mBase + mi * 16 + qr;
#pragma unroll
        for (int ni = 0; ni < 4; ni++) {
            int ccl = nBase + ni * 8 + qc * 2;
            stage[rl * STG_STRIDE + (ccl >> 1)] =
                pack_bf2(acc[mi][ni][0], acc[mi][ni][1]);
            stage[(rl + 8) * STG_STRIDE + (ccl >> 1)] =
                pack_bf2(acc[mi][ni][2], acc[mi][ni][3]);
        }
    }
    __syncthreads();

#pragma unroll
    for (int i = 0; i < 8; i++) {
        int cidx = tid + i * 256;
        int r = cidx >> 4, o = cidx & 15;
        int grow = rowBase + r;
        if (grow < N_EDGES) {
            uint4 v = *(uint4*)&stage[r * STG_STRIDE + o * 4];
            *((uint4*)(g_eah + (size_t)grow * 128) + o) = v;
        }
    }
}

// ---------------- CSR aggregation: one warp per node, 2-edge unroll ------------
__global__ void agg_csr() {
    int warp = (blockIdx.x * blockDim.x + threadIdx.x) >> 5;
    int lane = threadIdx.x & 31;
    if (warp >= N_NODES) return;

    int beg = g_ptr[warp], end = g_ptr[warp + 1];
    float4 acc = make_float4(0.f, 0.f, 0.f, 0.f);

    int e = beg;
    for (; e + 1 < end; e += 2) {
        int2 se0 = g_csr[e];
        int2 se1 = g_csr[e + 1];
        // 4 independent loads in flight (MLP=4)
        uint2 ev0 = *(const uint2*)&g_eah[(size_t)se0.y * C + lane * 4];
        uint2 mv0 = *(const uint2*)&g_mh[(size_t)se0.x * C + lane * 4];
        uint2 ev1 = *(const uint2*)&g_eah[(size_t)se1.y * C + lane * 4];
        uint2 mv1 = *(const uint2*)&g_mh[(size_t)se1.x * C + lane * 4];

        float2 e01 = __bfloat1622float2(*(bf162*)&ev0.x);
        float2 e23 = __bfloat1622float2(*(bf162*)&ev0.y);
        float2 m01 = __bfloat1622float2(*(bf162*)&mv0.x);
        float2 m23 = __bfloat1622float2(*(bf162*)&mv0.y);
        acc.x += fmaxf(m01.x + e01.x, 0.f);
        acc.y += fmaxf(m01.y + e01.y, 0.f);
        acc.z += fmaxf(m23.x + e23.x, 0.f);
        acc.w += fmaxf(m23.y + e23.y, 0.f);

        e01 = __bfloat1622float2(*(bf162*)&ev1.x);
        e23 = __bfloat1622float2(*(bf162*)&ev1.y);
        m01 = __bfloat1622float2(*(bf162*)&mv1.x);
        m23 = __bfloat1622float2(*(bf162*)&mv1.y);
        acc.x += fmaxf(m01.x + e01.x, 0.f);
        acc.y += fmaxf(m01.y + e01.y, 0.f);
        acc.z += fmaxf(m23.x + e23.x, 0.f);
        acc.w += fmaxf(m23.y + e23.y, 0.f);
    }
    if (e < end) {
        int2 se = g_csr[e];
        uint2 ev = *(const uint2*)&g_eah[(size_t)se.y * C + lane * 4];
        uint2 mv = *(const uint2*)&g_mh[(size_t)se.x * C + lane * 4];
        float2 e01 = __bfloat1622float2(*(bf162*)&ev.x);
        float2 e23 = __bfloat1622float2(*(bf162*)&ev.y);
        float2 m01 = __bfloat1622float2(*(bf162*)&mv.x);
        float2 m23 = __bfloat1622float2(*(bf162*)&mv.y);
        acc.x += fmaxf(m01.x + e01.x, 0.f);
        acc.y += fmaxf(m01.y + e01.y, 0.f);
        acc.z += fmaxf(m23.x + e23.x, 0.f);
        acc.w += fmaxf(m23.y + e23.y, 0.f);
    }
    float sc = g_invdeg[warp];
    uint2 st;
    st.x = pack_bf2(acc.x * sc, acc.y * sc);
    st.y = pack_bf2(acc.z * sc, acc.w * sc);
    *(uint2*)&g_aggh[(size_t)warp * C + lane * 4] = st;
}

// ---------------- GRU gates (bf16 gi/gh in, fp32 math) ----------------
__global__ void gru_gates(const float* __restrict__ hin,
                          float* __restrict__ hout, bf16* __restrict__ houth,
                          int last) {
    int idx = blockIdx.x * blockDim.x + threadIdx.x;   // 4-elem chunk index
    if (idx >= N_NODES * C / 4) return;
    int n = idx >> 5;
    int c4 = (idx & 31) * 4;
    const bf16* gib = g_gih + (size_t)n * 384;
    const bf16* ghb = g_ghh + (size_t)n * 384;

    uint2 u_ir = *(const uint2*)(gib + c4);
    uint2 u_iz = *(const uint2*)(gib + 128 + c4);
    uint2 u_in = *(const uint2*)(gib + 256 + c4);
    uint2 u_hr = *(const uint2*)(ghb + c4);
    uint2 u_hz = *(const uint2*)(ghb + 128 + c4);
    uint2 u_hn = *(const uint2*)(ghb + 256 + c4);
    float4 hv = *(const float4*)(hin + (size_t)idx * 4);

    float ir[4], iz[4], in_[4], hr[4], hz[4], hn[4];
    {
        float2 a, b;
        a = __bfloat1622float2(*(bf162*)&u_ir.x); b = __bfloat1622float2(*(bf162*)&u_ir.y);
        ir[0] = a.x; ir[1] = a.y; ir[2] = b.x; ir[3] = b.y;
        a = __bfloat1622float2(*(bf162*)&u_iz.x); b = __bfloat1622float2(*(bf162*)&u_iz.y);
        iz[0] = a.x; iz[1] = a.y; iz[2] = b.x; iz[3] = b.y;
        a = __bfloat1622float2(*(bf162*)&u_in.x); b = __bfloat1622float2(*(bf162*)&u_in.y);
        in_[0] = a.x; in_[1] = a.y; in_[2] = b.x; in_[3] = b.y;
        a = __bfloat1622float2(*(bf162*)&u_hr.x); b = __bfloat1622float2(*(bf162*)&u_hr.y);
        hr[0] = a.x; hr[1] = a.y; hr[2] = b.x; hr[3] = b.y;
        a = __bfloat1622float2(*(bf162*)&u_hz.x); b = __bfloat1622float2(*(bf162*)&u_hz.y);
        hz[0] = a.x; hz[1] = a.y; hz[2] = b.x; hz[3] = b.y;
        a = __bfloat1622float2(*(bf162*)&u_hn.x); b = __bfloat1622float2(*(bf162*)&u_hn.y);
        hn[0] = a.x; hn[1] = a.y; hn[2] = b.x; hn[3] = b.y;
    }

    float4 o;
#pragma unroll
    for (int j = 0; j < 4; j++) {
        float hj = (&hv.x)[j];
        float r = sigm(ir[j] + hr[j]);
        float z = sigm(iz[j] + hz[j]);
        float nn = tanhf(in_[j] + r * hn[j]);
        (&o.x)[j] = (1.f - z) * nn + z * hj;
    }

    if (last) {
        float4 xv = *(const float4*)(g_xh + (size_t)idx * 4);
        o.x = 0.5f * fmaxf(o.x, 0.f) + 0.5f * xv.x;
        o.y = 0.5f * fmaxf(o.y, 0.f) + 0.5f * xv.y;
        o.z = 0.5f * fmaxf(o.z, 0.f) + 0.5f * xv.z;
        o.w = 0.5f * fmaxf(o.w, 0.f) + 0.5f * xv.w;
        *(float4*)(hout + (size_t)idx * 4) = o;
    } else {
        *(float4*)(hout + (size_t)idx * 4) = o;
        uint2 st;
        st.x = pack_bf2(o.x, o.y);
        st.y = pack_bf2(o.z, o.w);
        *(uint2*)&houth[(size_t)idx * 4] = st;
    }
}

// ---------------- host ----------------
extern "C" void kernel_launch(void* const* d_in, const int* in_sizes, int n_in,
                              void* d_out, int out_size) {
    const float* x     = (const float*)d_in[0];
    const void*  eidx  = d_in[1];
    const float* eattr = (const float*)d_in[2];
    const float* gamma = (const float*)d_in[3];
    const float* beta  = (const float*)d_in[4];
    const float* edgeW = (const float*)d_in[5];
    const float* convW = (const float*)d_in[6];
    const float* w_ih  = (const float*)d_in[7];
    const float* w_hh  = (const float*)d_in[8];
    const float* b_ih  = (const float*)d_in[9];
    const float* b_hh  = (const float*)d_in[10];
    float* out = (float*)d_out;
    (void)in_sizes; (void)n_in; (void)out_size;

    float *xh, *h, *bias512;
    bf16 *xhh, *hh, *ghh, *gih, *mh, *aggh, *B0h, *B1h, *B2h;
    void* p;
    cudaGetSymbolAddress(&p, g_xh);      xh = (float*)p;
    cudaGetSymbolAddress(&p, g_xhh);     xhh = (bf16*)p;
    cudaGetSymbolAddress(&p, g_h);       h = (float*)p;
    cudaGetSymbolAddress(&p, g_hh);      hh = (bf16*)p;
    cudaGetSymbolAddress(&p, g_ghh);     ghh = (bf16*)p;
    cudaGetSymbolAddress(&p, g_gih);     gih = (bf16*)p;
    cudaGetSymbolAddress(&p, g_mh);      mh = (bf16*)p;
    cudaGetSymbolAddress(&p, g_aggh);    aggh = (bf16*)p;
    cudaGetSymbolAddress(&p, g_B0h);     B0h = (bf16*)p;
    cudaGetSymbolAddress(&p, g_B1h);     B1h = (bf16*)p;
    cudaGetSymbolAddress(&p, g_B2h);     B2h = (bf16*)p;
    cudaGetSymbolAddress(&p, g_bias512); bias512 = (float*)p;

    cudaFuncSetAttribute(gemm_bf16, cudaFuncAttributeMaxDynamicSharedMemorySize,
                         TILE_SMEM);

    // one-time stream/event setup (on the non-captured correctness call)
    static cudaStream_t s2 = nullptr, s3 = nullptr;
    static cudaEvent_t evF = nullptr, evJ = nullptr, evE = nullptr, evW = nullptr;
    if (s2 == nullptr) {
        cudaStreamCreateWithFlags(&s2, cudaStreamNonBlocking);
        cudaStreamCreateWithFlags(&s3, cudaStreamNonBlocking);
        cudaEventCreateWithFlags(&evF, cudaEventDisableTiming);
        cudaEventCreateWithFlags(&evJ, cudaEventDisableTiming);
        cudaEventCreateWithFlags(&evE, cudaEventDisableTiming);
        cudaEventCreateWithFlags(&evW, cudaEventDisableTiming);
    }

    const int NC = N_NODES * C;
    const int mtiles = (N_NODES + 127) / 128;      // 391
    const int etiles = (N_EDGES + 127) / 128;      // 4688

    // root
    detect_kernel<<<1, 64>>>((const long long*)eidx);
    cudaEventRecord(evF, 0);
    cudaStreamWaitEvent(s2, evF, 0);
    cudaStreamWaitEvent(s3, evF, 0);

    // ---- chain C (ea, edge order — depends only on inputs) on s3 ----
    prep_eW<<<8, 256, 0, s3>>>(edgeW);
    ea_gemm<<<etiles, 256, 0, s3>>>(eattr);
    cudaEventRecord(evE, s3);

    // ---- chain B (weights first, then graph/CSR) on s2 ----
    prep_weights<<<256, 256, 0, s2>>>(convW, w_ih, w_hh, b_hh);
    cudaEventRecord(evW, s2);
    zero_deg<<<(N_NODES + 255) / 256, 256, 0, s2>>>();
    normalize_edges<<<(N_EDGES + 255) / 256, 256, 0, s2>>>(eidx);
    scan_part<<<SCAN_BLOCKS, 256, 0, s2>>>();
    scan_top<<<1, 256, 0, s2>>>();
    scan_block<<<SCAN_BLOCKS, 256, 0, s2>>>();
    scatter_k<<<(N_EDGES + 255) / 256, 256, 0, s2>>>();
    cudaEventRecord(evJ, s2);

    // ---- chain A (BN + layer-0 GEMM1) on capture stream ----
    zero_bn<<<1, 128>>>();
    bn_stats<<<1024, 256>>>(x);
    bn_apply<<<(NC / 4 + 255) / 256, 256>>>(x, gamma, beta);
    cudaStreamWaitEvent(0, evW, 0);     // gemm1 needs B0h/bias512
    gemm_bf16<<<dim3(4, mtiles), 256, TILE_SMEM>>>(xhh, B0h, 512, bias512,
                                                   ghh, mh, 1, N_NODES);

    // join: agg needs CSR (B) + eah (C)
    cudaStreamWaitEvent(0, evJ, 0);
    cudaStreamWaitEvent(0, evE, 0);

    // layer 0
    agg_csr<<<(N_NODES + 7) / 8, 256>>>();
    gemm_bf16<<<dim3(3, mtiles), 256, TILE_SMEM>>>(aggh, B2h, 384, b_ih,
                                                   gih, nullptr, 0, N_NODES);
    gru_gates<<<(NC / 4 + 255) / 256, 256>>>(xh, h, hh, 0);

    // layer 1
    gemm_bf16<<<dim3(4, mtiles), 256, TILE_SMEM>>>(hh, B1h, 512, bias512,
                                                   ghh, mh, 1, N_NODES);
    agg_csr<<<(N_NODES + 7) / 8, 256>>>();
    gemm_bf16<<<dim3(3, mtiles), 256, TILE_SMEM>>>(aggh, B2h, 384, b_ih,
                                                   gih, nullptr, 0, N_NODES);
    gru_gates<<<(NC / 4 + 255) / 256, 256>>>(h, out, nullptr, 1);
}